// round 13
// baseline (speedup 1.0000x reference)
#include <cuda_runtime.h>
#include <math_constants.h>

#define N_PTS 500
#define NSTR 512
#define K12 12
#define KPP 4
#define NBLK 512
#define NTHR 256
#define KNN_BLKS 188

// ---------------- scratch (device globals; no allocation) ----------------
__device__ float g_cfT[N_PTS * 128];
__device__ float g_ctfT[N_PTS * 128];
__device__ float g_icT[N_PTS * 128];
__device__ float g_itT[N_PTS * 128];
__device__ int   g_inds[N_PTS * K12];
__device__ int   g_inds_self[N_PTS * K12];
__device__ int   g_inds_pp[N_PTS * KPP];
__device__ float g_wct[N_PTS * K12];
__device__ float g_wcc[N_PTS * K12];
__device__ float g_ws0[192];
__device__ float g_ws1[192];
__device__ float g_inv[2];
__device__ float g_cat[NSTR * 512];       // padded rows 500-511 stay 0 (zero-init)
__device__ float g_V[160 * 512];          // folded fuse2@fc weights
__device__ float g_bF[160];
__device__ float g_Weffp[2 * 1024 * 160]; // split-K partials of Wpn2@Wpn1
__device__ float g_beff[1024];
__device__ float g_F[160 * NSTR];         // init bF, RED-accumulated (stride 512)
__device__ float g_X2[1024 * NSTR];       // init beff, RED-accumulated
__device__ float g_X3[160 * NSTR];        // init bpn3, RED-accumulated

// ---------------- flag-based grid barrier (tight spin, replay-safe) -------
__device__ unsigned g_flag[8][NBLK];
__device__ unsigned g_bar_gen[8];

template <bool PAYLOAD>
__device__ __forceinline__ void gridbar(int slot) {
    __shared__ float s_red[2][8];
    __syncthreads();
    if (blockIdx.x == 0) {
        if (threadIdx.x == 0) {
            __threadfence();
            unsigned gen = *(volatile unsigned*)&g_bar_gen[slot];
            *(volatile unsigned*)&g_flag[slot][0] = gen + 1;
        }
        __syncthreads();
        unsigned gen = *(volatile unsigned*)&g_bar_gen[slot];
        for (int j = threadIdx.x; j < NBLK; j += NTHR)
            while (*(volatile unsigned*)&g_flag[slot][j] != gen + 1) {}
        __syncthreads();
        if (PAYLOAD) {
            int t = threadIdx.x;
            float v0 = (t < 192) ? g_ws0[t] : 0.0f;
            float v1 = (t < 192) ? g_ws1[t] : 0.0f;
#pragma unroll
            for (int off = 16; off > 0; off >>= 1) {
                v0 += __shfl_down_sync(0xffffffffu, v0, off);
                v1 += __shfl_down_sync(0xffffffffu, v1, off);
            }
            if ((t & 31) == 0) { s_red[0][t >> 5] = v0; s_red[1][t >> 5] = v1; }
            __syncthreads();
            if (t == 0) {
                float s0 = 0.0f, s1 = 0.0f;
#pragma unroll
                for (int i = 0; i < 8; i++) { s0 += s_red[0][i]; s1 += s_red[1][i]; }
                g_inv[0] = 1.0f / s0;
                g_inv[1] = 1.0f / s1;
            }
            __syncthreads();
        }
        if (threadIdx.x == 0) {
            __threadfence();
            *(volatile unsigned*)&g_bar_gen[slot] =
                *(volatile unsigned*)&g_bar_gen[slot] + 1;
        }
        __syncthreads();
    } else {
        if (threadIdx.x == 0) {
            __threadfence();
            unsigned gen = *(volatile unsigned*)&g_bar_gen[slot];
            *(volatile unsigned*)&g_flag[slot][blockIdx.x] = gen + 1;
            while (*(volatile unsigned*)&g_bar_gen[slot] == gen) {}
        }
        __syncthreads();
    }
}

// ---------------- shared memory union -------------------------------------
struct SmemKNN {
    float x0[N_PTS], y0[N_PTS], z0[N_PTS], w0[N_PTS];
    float x1[N_PTS], y1[N_PTS], z1[N_PTS], w1[N_PTS];
    float wsum[2][8];
};
struct SmemFeat { float W2s[128 * 64]; float xin[32 * 32]; float hid[64 * 32]; };
struct SmemGemm { float Ws[2][16][68]; float Xs[2][16][68]; };
union __align__(16) Smem {
    SmemKNN knn;
    SmemFeat feat;
    SmemGemm gemm;
};

// ---------------- warp-cooperative KNN ------------------------------------
template <int K, bool WCALC>
__device__ float knn_one(const float* __restrict__ rx, const float* __restrict__ ry,
                         const float* __restrict__ rz, const float* __restrict__ rr,
                         float qx, float qy, float qz,
                         int* __restrict__ outIdx, float* __restrict__ wOut, int q) {
    int lane = threadIdx.x & 31;
    float qq = qx * qx + qy * qy + qz * qz;
    float dist[K]; int idx[K];
#pragma unroll
    for (int t = 0; t < K; t++) { dist[t] = CUDART_INF_F; idx[t] = 0x7fffffff; }
    for (int r = lane; r < N_PTS; r += 32) {
        float d2 = qq - 2.0f * (qx * rx[r] + qy * ry[r] + qz * rz[r]) + rr[r];
        if (d2 < dist[K - 1]) {
            dist[K - 1] = d2; idx[K - 1] = r;
#pragma unroll
            for (int t = K - 1; t > 0; --t) {
                if (dist[t] < dist[t - 1]) {
                    float td = dist[t]; dist[t] = dist[t - 1]; dist[t - 1] = td;
                    int ti = idx[t]; idx[t] = idx[t - 1]; idx[t - 1] = ti;
                }
            }
        }
    }
    int mywin = 0;
#pragma unroll
    for (int t = 0; t < K; t++) {
        float bd = dist[0]; int bi = idx[0];
#pragma unroll
        for (int off = 16; off > 0; off >>= 1) {
            float od = __shfl_down_sync(0xffffffffu, bd, off);
            int oi = __shfl_down_sync(0xffffffffu, bi, off);
            if (od < bd || (od == bd && oi < bi)) { bd = od; bi = oi; }
        }
        bi = __shfl_sync(0xffffffffu, bi, 0);
        if (lane == 0) outIdx[q * K + t] = bi;
        if (lane == t) mywin = bi;
        if (idx[0] == bi) {
#pragma unroll
            for (int tt = 0; tt < K - 1; tt++) { dist[tt] = dist[tt + 1]; idx[tt] = idx[tt + 1]; }
            dist[K - 1] = CUDART_INF_F; idx[K - 1] = 0x7fffffff;
        }
    }
    float e = 0.0f;
    if (WCALC) {
        if (lane < K) {
            float dx = qx - rx[mywin], dy = qy - ry[mywin], dz = qz - rz[mywin];
            float d = sqrtf(dx * dx + dy * dy + dz * dz + 1e-12f);
            e = expf(-d);
            wOut[q * K + lane] = e;
        }
#pragma unroll
        for (int off = 16; off > 0; off >>= 1)
            e += __shfl_down_sync(0xffffffffu, e, off);
    }
    return e;
}

// ---------------- feature tile (2-layer 1x1 conv), point-major out --------
template <int IN_CH, bool CLOUD>
__device__ void dev_feat(int n0, const float* __restrict__ src,
                         const float* __restrict__ W1, const float* __restrict__ b1,
                         const float* __restrict__ W2, const float* __restrict__ b2,
                         float* __restrict__ out, Smem& sm) {
    int tid = threadIdx.x;
    if (CLOUD) {
        for (int i = tid; i < IN_CH * 32; i += NTHR) {
            int c = i >> 5, p = i & 31;
            sm.feat.xin[i] = (n0 + p < N_PTS) ? src[(n0 + p) * 3 + c] : 0.0f;
        }
    } else {
        for (int i = tid; i < IN_CH * 32; i += NTHR) {
            int c = i >> 5, p = i & 31;
            sm.feat.xin[i] = (n0 + p < N_PTS) ? src[c * N_PTS + n0 + p] : 0.0f;
        }
    }
    for (int i = tid; i < 128 * 64 / 4; i += NTHR)
        ((float4*)sm.feat.W2s)[i] = ((const float4*)W2)[i];
    __syncthreads();

    int pt = tid & 31, g = tid >> 5;
#pragma unroll
    for (int cc = 0; cc < 8; cc++) {
        int ch = g * 8 + cc;
        float h = b1[ch];
#pragma unroll
        for (int i = 0; i < IN_CH; i++)
            h = fmaf(W1[ch * IN_CH + i], sm.feat.xin[i * 32 + pt], h);
        sm.feat.hid[ch * 32 + pt] = (h > 0.0f) ? h : 0.01f * h;
    }
    __syncthreads();

    int ch0 = g * 16;
    float acc[16];
#pragma unroll
    for (int i = 0; i < 16; i++) acc[i] = b2[ch0 + i];
#pragma unroll 4
    for (int j = 0; j < 64; j++) {
        float h = sm.feat.hid[j * 32 + pt];
#pragma unroll
        for (int i = 0; i < 16; i++)
            acc[i] = fmaf(sm.feat.W2s[(ch0 + i) * 64 + j], h, acc[i]);
    }
    int n = n0 + pt;
    if (n < N_PTS) {
#pragma unroll
        for (int i = 0; i < 16; i++) out[n * 128 + ch0 + i] = acc[i];
    }
    __syncthreads();
}

// ---------------- double-buffered 64x64 GEMM tile -------------------------
// XMODE: 0 plain X[k*xstride+col]; 1 xT X[col*xstride+k]; 2 lrelu(plain)
// OUTMODE: 2 store raw; 3 atomicAdd(RED) raw.  WSUM: W = Wa + Wb
// PADX: X buffer padded -> unguarded float4 loads (XMODE 0/2 only)
// GUARDK: kLen not slab-aligned -> zero-guard W and X rows beyond kLen
template <int XMODE, int OUTMODE, int WSUM, int PADX, int GUARDK>
__device__ void gemm_tile(const float* __restrict__ Wa, const float* __restrict__ Wb,
                          int KW, int kLen,
                          const float* __restrict__ X, int xstride, int xn0, int Nx,
                          float* __restrict__ Y, int ystride,
                          int M, int Nout, int m0, int n0, Smem& sm) {
    int tid = threadIdx.x;
    int ty = tid >> 4, tx = tid & 15;
    float acc[4][4] = {};
    float4 pw, px4;
    float pxs[4];
    int wrow = (tid * 4) >> 4, wcol = (tid * 4) & 15;
    int xkr = tid >> 4, xc4 = (tid & 15) * 4;

    auto loadW = [&](int k0) {
        if (m0 + wrow < M) {
            if (GUARDK) {
                const float* wr = &Wa[(m0 + wrow) * KW + k0 + wcol];
                const float* wr2 = WSUM ? &Wb[(m0 + wrow) * KW + k0 + wcol] : nullptr;
                pw.x = (k0 + wcol + 0 < kLen) ? (WSUM ? wr[0] + wr2[0] : wr[0]) : 0.0f;
                pw.y = (k0 + wcol + 1 < kLen) ? (WSUM ? wr[1] + wr2[1] : wr[1]) : 0.0f;
                pw.z = (k0 + wcol + 2 < kLen) ? (WSUM ? wr[2] + wr2[2] : wr[2]) : 0.0f;
                pw.w = (k0 + wcol + 3 < kLen) ? (WSUM ? wr[3] + wr2[3] : wr[3]) : 0.0f;
            } else {
                pw = *(const float4*)&Wa[(m0 + wrow) * KW + k0 + wcol];
                if (WSUM) {
                    float4 w2 = *(const float4*)&Wb[(m0 + wrow) * KW + k0 + wcol];
                    pw.x += w2.x; pw.y += w2.y; pw.z += w2.z; pw.w += w2.w;
                }
            }
        } else {
            pw = make_float4(0.f, 0.f, 0.f, 0.f);
        }
    };
    auto loadX = [&](int k0) {
        if (XMODE == 1) {
#pragma unroll
            for (int i = 0; i < 4; i++) {
                int l = tid + i * NTHR;
                int kr = l & 15, col = l >> 4;
                pxs[i] = (xn0 + col < Nx) ? X[(xn0 + col) * xstride + k0 + kr] : 0.0f;
            }
        } else if (PADX) {
            if (GUARDK && k0 + xkr >= kLen) {
                px4 = make_float4(0.f, 0.f, 0.f, 0.f);
            } else {
                px4 = *(const float4*)&X[(k0 + xkr) * xstride + xn0 + xc4];
            }
            if (XMODE == 2) {
                px4.x = (px4.x > 0.0f) ? px4.x : 0.01f * px4.x;
                px4.y = (px4.y > 0.0f) ? px4.y : 0.01f * px4.y;
                px4.z = (px4.z > 0.0f) ? px4.z : 0.01f * px4.z;
                px4.w = (px4.w > 0.0f) ? px4.w : 0.01f * px4.w;
            }
        } else {
            const float* row = &X[(k0 + xkr) * xstride + xn0];
            px4.x = (xn0 + xc4 + 0 < Nx) ? row[xc4 + 0] : 0.0f;
            px4.y = (xn0 + xc4 + 1 < Nx) ? row[xc4 + 1] : 0.0f;
            px4.z = (xn0 + xc4 + 2 < Nx) ? row[xc4 + 2] : 0.0f;
            px4.w = (xn0 + xc4 + 3 < Nx) ? row[xc4 + 3] : 0.0f;
            if (XMODE == 2) {
                px4.x = (px4.x > 0.0f) ? px4.x : 0.01f * px4.x;
                px4.y = (px4.y > 0.0f) ? px4.y : 0.01f * px4.y;
                px4.z = (px4.z > 0.0f) ? px4.z : 0.01f * px4.z;
                px4.w = (px4.w > 0.0f) ? px4.w : 0.01f * px4.w;
            }
        }
    };

    loadW(0); loadX(0);
    int p = 0;
    for (int k0 = 0; k0 < kLen; k0 += 16) {
        sm.gemm.Ws[p][wcol + 0][wrow] = pw.x;
        sm.gemm.Ws[p][wcol + 1][wrow] = pw.y;
        sm.gemm.Ws[p][wcol + 2][wrow] = pw.z;
        sm.gemm.Ws[p][wcol + 3][wrow] = pw.w;
        if (XMODE == 1) {
#pragma unroll
            for (int i = 0; i < 4; i++) {
                int l = tid + i * NTHR;
                sm.gemm.Xs[p][l & 15][l >> 4] = pxs[i];
            }
        } else {
            *(float4*)&sm.gemm.Xs[p][xkr][xc4] = px4;
        }
        __syncthreads();
        if (k0 + 16 < kLen) { loadW(k0 + 16); loadX(k0 + 16); }
#pragma unroll
        for (int kk = 0; kk < 16; kk++) {
            float4 a4 = *(const float4*)&sm.gemm.Ws[p][kk][ty * 4];
            float4 b4 = *(const float4*)&sm.gemm.Xs[p][kk][tx * 4];
            float a[4] = {a4.x, a4.y, a4.z, a4.w};
            float bb[4] = {b4.x, b4.y, b4.z, b4.w};
#pragma unroll
            for (int i = 0; i < 4; i++)
#pragma unroll
                for (int j = 0; j < 4; j++)
                    acc[i][j] = fmaf(a[i], bb[j], acc[i][j]);
        }
        p ^= 1;
    }
#pragma unroll
    for (int i = 0; i < 4; i++) {
        int m = m0 + ty * 4 + i;
        if (m >= M) continue;
#pragma unroll
        for (int j = 0; j < 4; j++) {
            int n = n0 + tx * 4 + j;
            if (n >= Nout) continue;
            if (OUTMODE == 3) atomicAdd(&Y[m * ystride + n], acc[i][j]);
            else              Y[m * ystride + n] = acc[i][j];
        }
    }
}

// --------------------------- megakernel -----------------------------------
__global__ void __launch_bounds__(NTHR, 4)
mega_kernel(const float* __restrict__ img, const float* __restrict__ cloud,
            const float* __restrict__ img_tar, const float* __restrict__ cloud_tar,
            const float* __restrict__ cur_feat, const float* __restrict__ tgt_feat,
            const float* __restrict__ Wc1, const float* __restrict__ bc1,
            const float* __restrict__ Wc2, const float* __restrict__ bc2,
            const float* __restrict__ Wp1, const float* __restrict__ bp1,
            const float* __restrict__ Wp2, const float* __restrict__ bp2,
            const float* __restrict__ Wfc1, const float* __restrict__ bfc1,
            const float* __restrict__ Wfc2, const float* __restrict__ bfc2,
            const float* __restrict__ Wfu2, const float* __restrict__ bfu2,
            const float* __restrict__ Wpn1, const float* __restrict__ bpn1,
            const float* __restrict__ Wpn2, const float* __restrict__ bpn2,
            const float* __restrict__ Wpn3, const float* __restrict__ bpn3,
            float* __restrict__ out) {
    __shared__ Smem sm;
    int b = blockIdx.x;
    int tid = threadIdx.x;

    // ---- P0: KNN (0-187) || feat (188-251) || Weff fold x2 (252-347)
    //          || V fold (348-371) || beff (372-375) || bF (376)
    if (b < KNN_BLKS) {
        SmemKNN& k = sm.knn;
        for (int i = tid; i < N_PTS; i += NTHR) {
            float x = cloud[i * 3 + 0], y = cloud[i * 3 + 1], z = cloud[i * 3 + 2];
            k.x0[i] = x; k.y0[i] = y; k.z0[i] = z; k.w0[i] = x * x + y * y + z * z;
            x = cloud_tar[i * 3 + 0]; y = cloud_tar[i * 3 + 1]; z = cloud_tar[i * 3 + 2];
            k.x1[i] = x; k.y1[i] = y; k.z1[i] = z; k.w1[i] = x * x + y * y + z * z;
        }
        if (tid < 16) k.wsum[tid >> 3][tid & 7] = 0.0f;
        __syncthreads();
        int w = tid >> 5;
        int qid = b * 8 + w;
        if (qid < 1500) {
            int task = (qid < 500) ? 0 : (qid < 1000 ? 1 : 2);
            int q = qid - task * 500;
            if (task == 0) {
                float s = knn_one<K12, true>(k.x0, k.y0, k.z0, k.w0,
                                             k.x1[q], k.y1[q], k.z1[q],
                                             g_inds, g_wct, q);
                if ((tid & 31) == 0) k.wsum[0][w] = s;
            } else if (task == 1) {
                float s = knn_one<K12, true>(k.x1, k.y1, k.z1, k.w1,
                                             k.x1[q], k.y1[q], k.z1[q],
                                             g_inds_self, g_wcc, q);
                if ((tid & 31) == 0) k.wsum[1][w] = s;
            } else {
                knn_one<KPP, false>(k.x1, k.y1, k.z1, k.w1,
                                    k.x0[q], k.y0[q], k.z0[q],
                                    g_inds_pp, nullptr, q);
            }
        }
        __syncthreads();
        if (tid == 0) {
            float s0 = 0.0f, s1 = 0.0f;
#pragma unroll
            for (int i = 0; i < 8; i++) { s0 += k.wsum[0][i]; s1 += k.wsum[1][i]; }
            g_ws0[b] = s0; g_ws1[b] = s1;
        }
    } else if (b < 252) {
        int u = b - KNN_BLKS;
        int task = u >> 4, n0 = (u & 15) * 32;
        if (task == 0)      dev_feat<3, true>(n0, cloud_tar, Wp1, bp1, Wp2, bp2, g_cfT, sm);
        else if (task == 1) dev_feat<3, true>(n0, cloud, Wp1, bp1, Wp2, bp2, g_ctfT, sm);
        else if (task == 2) dev_feat<32, false>(n0, img_tar, Wc1, bc1, Wc2, bc2, g_icT, sm);
        else                dev_feat<32, false>(n0, img, Wc1, bc1, Wc2, bc2, g_itT, sm);
    } else if (b < 348) {
        int u = b - 252;  // 96 blocks: split-K x2 of Wpn2@Wpn1, 48 tiles each
        int half = u & 1, t = u >> 1;  // t: 0..47 = 16m x 3n
        gemm_tile<0, 2, 0, 0, 0>(Wpn2 + half * 128, nullptr, 256, 128,
                                 Wpn1 + half * 128 * 160, 160, (t % 3) * 64, 160,
                                 g_Weffp + half * 1024 * 160, 160, 1024, 160,
                                 (t / 3) * 64, (t % 3) * 64, sm);
    } else if (b < 372) {
        int u = b - 348;  // V fold: 2 halves x 3m x 4n, K=64 (exact-fit X)
        int v1 = (u >= 12) ? 1 : 0; int t = u - v1 * 12;
        gemm_tile<0, 2, 0, 1, 0>(Wfu2 + v1 * 64, nullptr, 128, 64,
                                 v1 ? Wfc1 : Wfc2, 256, (t % 4) * 64, 256,
                                 g_V, 512, 160, 512,
                                 (t / 4) * 64, (t % 4) * 64 + v1 * 256, sm);
    } else if (b < 376) {
        int base = (b - 372) * 256;
        for (int m = base + tid; m < base + 256; m += NTHR) {
            float a0 = 0.0f, a1 = 0.0f, a2 = 0.0f, a3 = 0.0f;
            const float* wr = Wpn2 + m * 256;
            for (int kk = 0; kk < 256; kk += 4) {
                a0 = fmaf(wr[kk], bpn1[kk], a0);
                a1 = fmaf(wr[kk + 1], bpn1[kk + 1], a1);
                a2 = fmaf(wr[kk + 2], bpn1[kk + 2], a2);
                a3 = fmaf(wr[kk + 3], bpn1[kk + 3], a3);
            }
            g_beff[m] = bpn2[m] + ((a0 + a1) + (a2 + a3));
        }
    } else if (b == 376) {
        if (tid < 160) {
            float a0 = 0.0f, a1 = 0.0f;
            const float* wr = Wfu2 + tid * 128;
            for (int kk = 0; kk < 64; kk++) {
                a0 = fmaf(wr[kk], bfc2[kk], a0);
                a1 = fmaf(wr[64 + kk], bfc1[kk], a1);
            }
            g_bF[tid] = bfu2[tid] + a0 + a1;
        }
    }
    gridbar<true>(0);  // payload: publishes g_inv[0..1]

    // ---- P1: pool1 (blocks 0-499) || init F = bF over stride-512 (500-511)
    if (b < 500) {
        float inv = g_inv[0];
        int half = tid >> 7, ch = tid & 127;
        int n = b;
        if (half == 0) {
            float mi = -CUDART_INF_F;
#pragma unroll
            for (int kk = 0; kk < K12; kk++) {
                int i = g_inds[n * K12 + kk];
                mi = fmaxf(mi, g_itT[i * 128 + ch] * (g_wct[n * K12 + kk] * inv));
            }
            g_cat[n * 512 + 256 + ch] = g_icT[n * 128 + ch] - mi;  // img_diff
        } else {
            float mp = -CUDART_INF_F;
#pragma unroll
            for (int kk = 0; kk < K12; kk++) {
                int i = g_inds[n * K12 + kk];
                mp = fmaxf(mp, g_ctfT[i * 128 + ch] * (g_wct[n * K12 + kk] * inv));
            }
            g_cat[n * 512 + ch] = g_cfT[n * 128 + ch] - mp;  // cloud_diff
        }
    } else {
        for (int e = (b - 500) * NTHR + tid; e < 160 * NSTR; e += 12 * NTHR)
            g_F[e] = g_bF[e >> 9];
    }
    gridbar<false>(1);

    // ---- P2: pool2 (blocks 0-499)
    if (b < 500) {
        float inv = g_inv[1];
        int half = tid >> 7, ch = tid & 127;
        int n = b;
        if (half == 0) {
            float msid = -CUDART_INF_F;
#pragma unroll
            for (int kk = 0; kk < K12; kk++) {
                int i = g_inds_self[n * K12 + kk];
                msid = fmaxf(msid, g_cat[i * 512 + 256 + ch] * (g_wcc[n * K12 + kk] * inv));
            }
            g_cat[n * 512 + 128 + ch] = msid;  // sid
        } else {
            float mspd = -CUDART_INF_F;
#pragma unroll
            for (int kk = 0; kk < K12; kk++) {
                int i = g_inds_self[n * K12 + kk];
                mspd = fmaxf(mspd, g_cat[i * 512 + ch] * (g_wcc[n * K12 + kk] * inv));
            }
            g_cat[n * 512 + 384 + ch] = mspd;  // spd
        }
    }
    gridbar<false>(2);

    // ---- P3: F += V @ cat^T  (split-K x16, blocks 0-383)
    //          || init X2 = beff, X3 = bpn3 (blocks 384-511)
    if (b < 384) {
        int slab = b & 15, t = b >> 4;  // t: 0..23 = 3m x 8n
        int kb = slab * 32;
        gemm_tile<1, 3, 0, 0, 0>(g_V + kb, nullptr, 512, 32,
                                 g_cat + kb, 512, (t & 7) * 64, 512,
                                 g_F, NSTR, 160, 512, (t >> 3) * 64, (t & 7) * 64, sm);
    } else {
        int u = b - 384;  // 128 blocks
        for (int e = u * NTHR + tid; e < 1024 * NSTR; e += 128 * NTHR)
            g_X2[e] = g_beff[e >> 9];
        for (int e = u * NTHR + tid; e < 160 * NSTR; e += 128 * NTHR)
            g_X3[e] = bpn3[e >> 9];
    }
    gridbar<false>(3);

    // ---- P4: X2 += (Weffp0+Weffp1) @ F  (split-K x4, K=40 guarded; 512 blocks)
    {
        int slab = b & 3, t = b >> 2;  // t: 0..127 = 16m x 8n
        int kb = slab * 40;
        gemm_tile<0, 3, 1, 1, 1>(g_Weffp + kb, g_Weffp + 1024 * 160 + kb,
                                 160, 40,
                                 g_F + kb * NSTR, NSTR, (t & 7) * 64, 512,
                                 g_X2, NSTR, 1024, 512, (t >> 3) * 64, (t & 7) * 64, sm);
    }
    gridbar<false>(4);

    // ---- P5: X3 += Wpn3 @ lrelu(X2)  (split-K x16, K=64; blocks 0-383)
    if (b < 384) {
        int slab = b & 15, t = b >> 4;  // t: 0..23 = 3m x 8n
        gemm_tile<2, 3, 0, 1, 0>(Wpn3 + slab * 64, nullptr, 1024, 64,
                                 g_X2 + slab * 64 * NSTR, NSTR, (t & 7) * 64, 512,
                                 g_X3, NSTR, 160, 512, (t >> 3) * 64, (t & 7) * 64, sm);
    }
    gridbar<false>(5);

    // ---- P6: final gather-mean (blocks 0-499)
    if (b < 500 && tid < 160) {
        int n = b;
        float s = 0.0f;
#pragma unroll
        for (int kk = 0; kk < KPP; kk++) {
            int i = g_inds_pp[n * KPP + kk];
            s += tgt_feat[tid * N_PTS + i] * g_X3[tid * NSTR + i];
        }
        out[tid * N_PTS + n] = cur_feat[tid * N_PTS + n] + 0.25f * s;
    }
}

// --------------------------------------------------------------------------
extern "C" void kernel_launch(void* const* d_in, const int* in_sizes, int n_in,
                              void* d_out, int out_size) {
    mega_kernel<<<NBLK, NTHR>>>(
        (const float*)d_in[0],  (const float*)d_in[1],
        (const float*)d_in[2],  (const float*)d_in[3],
        (const float*)d_in[4],  (const float*)d_in[5],
        (const float*)d_in[6],  (const float*)d_in[7],
        (const float*)d_in[8],  (const float*)d_in[9],
        (const float*)d_in[10], (const float*)d_in[11],
        (const float*)d_in[12], (const float*)d_in[13],
        (const float*)d_in[14], (const float*)d_in[15],
        (const float*)d_in[16], (const float*)d_in[17],
        (const float*)d_in[18], (const float*)d_in[19],
        (const float*)d_in[20], (const float*)d_in[21],
        (const float*)d_in[22], (const float*)d_in[23],
        (const float*)d_in[24], (const float*)d_in[25],
        (float*)d_out);
}

// round 14
// speedup vs baseline: 1.0379x; 1.0379x over previous
#include <cuda_runtime.h>
#include <math_constants.h>

#define N_PTS 500
#define NSTR 512
#define K12 12
#define KPP 4
#define NBLK 512
#define NTHR 256
#define KNN_BLKS 188

// ---------------- scratch (device globals; no allocation) ----------------
__device__ float g_cfT[N_PTS * 128];
__device__ float g_ctfT[N_PTS * 128];
__device__ float g_icT[N_PTS * 128];
__device__ float g_itT[N_PTS * 128];
__device__ int   g_inds[N_PTS * K12];
__device__ int   g_inds_self[N_PTS * K12];
__device__ int   g_inds_pp[N_PTS * KPP];
__device__ float g_wct[N_PTS * K12];
__device__ float g_wcc[N_PTS * K12];
__device__ float g_ws0[192];
__device__ float g_ws1[192];
__device__ float g_inv[2];
__device__ float g_cat[NSTR * 512];       // padded rows 500-511 stay 0 (zero-init)
__device__ float g_V[160 * 512];          // folded fuse2@fc weights
__device__ float g_bF[160];
__device__ float g_Weffp[2 * 1024 * 160]; // split-K partials of Wpn2@Wpn1
__device__ float g_beff[1024];
__device__ float g_F[160 * NSTR];         // init bF, RED-accumulated (stride 512)
__device__ float g_X2[1024 * NSTR];       // init beff, RED-accumulated
__device__ float g_X3[160 * NSTR];        // init bpn3, RED-accumulated

// ---------------- flag-based grid barrier (tight spin, replay-safe) -------
__device__ unsigned g_flag[8][NBLK];
__device__ unsigned g_bar_gen[8];

template <bool PAYLOAD>
__device__ __forceinline__ void gridbar(int slot) {
    __shared__ float s_red[2][8];
    __syncthreads();
    if (blockIdx.x == 0) {
        if (threadIdx.x == 0) {
            __threadfence();
            unsigned gen = *(volatile unsigned*)&g_bar_gen[slot];
            *(volatile unsigned*)&g_flag[slot][0] = gen + 1;
        }
        __syncthreads();
        unsigned gen = *(volatile unsigned*)&g_bar_gen[slot];
        for (int j = threadIdx.x; j < NBLK; j += NTHR)
            while (*(volatile unsigned*)&g_flag[slot][j] != gen + 1) {}
        __syncthreads();
        if (PAYLOAD) {
            int t = threadIdx.x;
            float v0 = (t < 192) ? g_ws0[t] : 0.0f;
            float v1 = (t < 192) ? g_ws1[t] : 0.0f;
#pragma unroll
            for (int off = 16; off > 0; off >>= 1) {
                v0 += __shfl_down_sync(0xffffffffu, v0, off);
                v1 += __shfl_down_sync(0xffffffffu, v1, off);
            }
            if ((t & 31) == 0) { s_red[0][t >> 5] = v0; s_red[1][t >> 5] = v1; }
            __syncthreads();
            if (t == 0) {
                float s0 = 0.0f, s1 = 0.0f;
#pragma unroll
                for (int i = 0; i < 8; i++) { s0 += s_red[0][i]; s1 += s_red[1][i]; }
                g_inv[0] = 1.0f / s0;
                g_inv[1] = 1.0f / s1;
            }
            __syncthreads();
        }
        if (threadIdx.x == 0) {
            __threadfence();
            *(volatile unsigned*)&g_bar_gen[slot] =
                *(volatile unsigned*)&g_bar_gen[slot] + 1;
        }
        __syncthreads();
    } else {
        if (threadIdx.x == 0) {
            __threadfence();
            unsigned gen = *(volatile unsigned*)&g_bar_gen[slot];
            *(volatile unsigned*)&g_flag[slot][blockIdx.x] = gen + 1;
            while (*(volatile unsigned*)&g_bar_gen[slot] == gen) {}
        }
        __syncthreads();
    }
}

// ---------------- shared memory union -------------------------------------
struct SmemKNN {
    float x0[N_PTS], y0[N_PTS], z0[N_PTS], w0[N_PTS];
    float x1[N_PTS], y1[N_PTS], z1[N_PTS], w1[N_PTS];
    float wsum[2][8];
};
struct SmemFeat { float W2s[128 * 64]; float xin[32 * 32]; float hid[64 * 32]; };
struct SmemGemm { float Ws[2][16][68]; float Xs[2][16][68]; };
union __align__(16) Smem {
    SmemKNN knn;
    SmemFeat feat;
    SmemGemm gemm;
};

// ---------------- warp-cooperative KNN ------------------------------------
template <int K, bool WCALC>
__device__ float knn_one(const float* __restrict__ rx, const float* __restrict__ ry,
                         const float* __restrict__ rz, const float* __restrict__ rr,
                         float qx, float qy, float qz,
                         int* __restrict__ outIdx, float* __restrict__ wOut, int q) {
    int lane = threadIdx.x & 31;
    float qq = qx * qx + qy * qy + qz * qz;
    float dist[K]; int idx[K];
#pragma unroll
    for (int t = 0; t < K; t++) { dist[t] = CUDART_INF_F; idx[t] = 0x7fffffff; }
    for (int r = lane; r < N_PTS; r += 32) {
        float d2 = qq - 2.0f * (qx * rx[r] + qy * ry[r] + qz * rz[r]) + rr[r];
        if (d2 < dist[K - 1]) {
            dist[K - 1] = d2; idx[K - 1] = r;
#pragma unroll
            for (int t = K - 1; t > 0; --t) {
                if (dist[t] < dist[t - 1]) {
                    float td = dist[t]; dist[t] = dist[t - 1]; dist[t - 1] = td;
                    int ti = idx[t]; idx[t] = idx[t - 1]; idx[t - 1] = ti;
                }
            }
        }
    }
    int mywin = 0;
#pragma unroll
    for (int t = 0; t < K; t++) {
        float bd = dist[0]; int bi = idx[0];
#pragma unroll
        for (int off = 16; off > 0; off >>= 1) {
            float od = __shfl_down_sync(0xffffffffu, bd, off);
            int oi = __shfl_down_sync(0xffffffffu, bi, off);
            if (od < bd || (od == bd && oi < bi)) { bd = od; bi = oi; }
        }
        bi = __shfl_sync(0xffffffffu, bi, 0);
        if (lane == 0) outIdx[q * K + t] = bi;
        if (lane == t) mywin = bi;
        if (idx[0] == bi) {
#pragma unroll
            for (int tt = 0; tt < K - 1; tt++) { dist[tt] = dist[tt + 1]; idx[tt] = idx[tt + 1]; }
            dist[K - 1] = CUDART_INF_F; idx[K - 1] = 0x7fffffff;
        }
    }
    float e = 0.0f;
    if (WCALC) {
        if (lane < K) {
            float dx = qx - rx[mywin], dy = qy - ry[mywin], dz = qz - rz[mywin];
            float d = sqrtf(dx * dx + dy * dy + dz * dz + 1e-12f);
            e = expf(-d);
            wOut[q * K + lane] = e;
        }
#pragma unroll
        for (int off = 16; off > 0; off >>= 1)
            e += __shfl_down_sync(0xffffffffu, e, off);
    }
    return e;
}

// ---------------- feature tile (2-layer 1x1 conv), point-major out --------
template <int IN_CH, bool CLOUD>
__device__ void dev_feat(int n0, const float* __restrict__ src,
                         const float* __restrict__ W1, const float* __restrict__ b1,
                         const float* __restrict__ W2, const float* __restrict__ b2,
                         float* __restrict__ out, Smem& sm) {
    int tid = threadIdx.x;
    if (CLOUD) {
        for (int i = tid; i < IN_CH * 32; i += NTHR) {
            int c = i >> 5, p = i & 31;
            sm.feat.xin[i] = (n0 + p < N_PTS) ? src[(n0 + p) * 3 + c] : 0.0f;
        }
    } else {
        for (int i = tid; i < IN_CH * 32; i += NTHR) {
            int c = i >> 5, p = i & 31;
            sm.feat.xin[i] = (n0 + p < N_PTS) ? src[c * N_PTS + n0 + p] : 0.0f;
        }
    }
    for (int i = tid; i < 128 * 64 / 4; i += NTHR)
        ((float4*)sm.feat.W2s)[i] = ((const float4*)W2)[i];
    __syncthreads();

    int pt = tid & 31, g = tid >> 5;
#pragma unroll
    for (int cc = 0; cc < 8; cc++) {
        int ch = g * 8 + cc;
        float h = b1[ch];
#pragma unroll
        for (int i = 0; i < IN_CH; i++)
            h = fmaf(W1[ch * IN_CH + i], sm.feat.xin[i * 32 + pt], h);
        sm.feat.hid[ch * 32 + pt] = (h > 0.0f) ? h : 0.01f * h;
    }
    __syncthreads();

    int ch0 = g * 16;
    float acc[16];
#pragma unroll
    for (int i = 0; i < 16; i++) acc[i] = b2[ch0 + i];
#pragma unroll 4
    for (int j = 0; j < 64; j++) {
        float h = sm.feat.hid[j * 32 + pt];
#pragma unroll
        for (int i = 0; i < 16; i++)
            acc[i] = fmaf(sm.feat.W2s[(ch0 + i) * 64 + j], h, acc[i]);
    }
    int n = n0 + pt;
    if (n < N_PTS) {
#pragma unroll
        for (int i = 0; i < 16; i++) out[n * 128 + ch0 + i] = acc[i];
    }
    __syncthreads();
}

// ---------------- double-buffered 64x64 GEMM tile -------------------------
// XMODE: 0 plain X[k*xstride+col]; 1 xT X[col*xstride+k]; 2 lrelu(plain)
// OUTMODE: 2 store raw; 3 atomicAdd(RED) raw.  WSUM: W = Wa + Wb
// PADX: X buffer padded -> unguarded float4 loads (XMODE 0/2 only)
template <int XMODE, int OUTMODE, int WSUM, int PADX>
__device__ void gemm_tile(const float* __restrict__ Wa, const float* __restrict__ Wb,
                          int KW, int kLen,
                          const float* __restrict__ X, int xstride, int xn0, int Nx,
                          float* __restrict__ Y, int ystride,
                          int M, int Nout, int m0, int n0, Smem& sm) {
    int tid = threadIdx.x;
    int ty = tid >> 4, tx = tid & 15;
    float acc[4][4] = {};
    float4 pw, px4;
    float pxs[4];
    int wrow = (tid * 4) >> 4, wcol = (tid * 4) & 15;
    int xkr = tid >> 4, xc4 = (tid & 15) * 4;

    auto loadW = [&](int k0) {
        if (m0 + wrow < M) {
            pw = *(const float4*)&Wa[(m0 + wrow) * KW + k0 + wcol];
            if (WSUM) {
                float4 w2 = *(const float4*)&Wb[(m0 + wrow) * KW + k0 + wcol];
                pw.x += w2.x; pw.y += w2.y; pw.z += w2.z; pw.w += w2.w;
            }
        } else {
            pw = make_float4(0.f, 0.f, 0.f, 0.f);
        }
    };
    auto loadX = [&](int k0) {
        if (XMODE == 1) {
#pragma unroll
            for (int i = 0; i < 4; i++) {
                int l = tid + i * NTHR;
                int kr = l & 15, col = l >> 4;
                pxs[i] = (xn0 + col < Nx) ? X[(xn0 + col) * xstride + k0 + kr] : 0.0f;
            }
        } else if (PADX) {
            px4 = *(const float4*)&X[(k0 + xkr) * xstride + xn0 + xc4];
            if (XMODE == 2) {
                px4.x = (px4.x > 0.0f) ? px4.x : 0.01f * px4.x;
                px4.y = (px4.y > 0.0f) ? px4.y : 0.01f * px4.y;
                px4.z = (px4.z > 0.0f) ? px4.z : 0.01f * px4.z;
                px4.w = (px4.w > 0.0f) ? px4.w : 0.01f * px4.w;
            }
        } else {
            const float* row = &X[(k0 + xkr) * xstride + xn0];
            px4.x = (xn0 + xc4 + 0 < Nx) ? row[xc4 + 0] : 0.0f;
            px4.y = (xn0 + xc4 + 1 < Nx) ? row[xc4 + 1] : 0.0f;
            px4.z = (xn0 + xc4 + 2 < Nx) ? row[xc4 + 2] : 0.0f;
            px4.w = (xn0 + xc4 + 3 < Nx) ? row[xc4 + 3] : 0.0f;
            if (XMODE == 2) {
                px4.x = (px4.x > 0.0f) ? px4.x : 0.01f * px4.x;
                px4.y = (px4.y > 0.0f) ? px4.y : 0.01f * px4.y;
                px4.z = (px4.z > 0.0f) ? px4.z : 0.01f * px4.z;
                px4.w = (px4.w > 0.0f) ? px4.w : 0.01f * px4.w;
            }
        }
    };

    loadW(0); loadX(0);
    int p = 0;
    for (int k0 = 0; k0 < kLen; k0 += 16) {
        sm.gemm.Ws[p][wcol + 0][wrow] = pw.x;
        sm.gemm.Ws[p][wcol + 1][wrow] = pw.y;
        sm.gemm.Ws[p][wcol + 2][wrow] = pw.z;
        sm.gemm.Ws[p][wcol + 3][wrow] = pw.w;
        if (XMODE == 1) {
#pragma unroll
            for (int i = 0; i < 4; i++) {
                int l = tid + i * NTHR;
                sm.gemm.Xs[p][l & 15][l >> 4] = pxs[i];
            }
        } else {
            *(float4*)&sm.gemm.Xs[p][xkr][xc4] = px4;
        }
        __syncthreads();
        if (k0 + 16 < kLen) { loadW(k0 + 16); loadX(k0 + 16); }
#pragma unroll
        for (int kk = 0; kk < 16; kk++) {
            float4 a4 = *(const float4*)&sm.gemm.Ws[p][kk][ty * 4];
            float4 b4 = *(const float4*)&sm.gemm.Xs[p][kk][tx * 4];
            float a[4] = {a4.x, a4.y, a4.z, a4.w};
            float bb[4] = {b4.x, b4.y, b4.z, b4.w};
#pragma unroll
            for (int i = 0; i < 4; i++)
#pragma unroll
                for (int j = 0; j < 4; j++)
                    acc[i][j] = fmaf(a[i], bb[j], acc[i][j]);
        }
        p ^= 1;
    }
#pragma unroll
    for (int i = 0; i < 4; i++) {
        int m = m0 + ty * 4 + i;
        if (m >= M) continue;
#pragma unroll
        for (int j = 0; j < 4; j++) {
            int n = n0 + tx * 4 + j;
            if (n >= Nout) continue;
            if (OUTMODE == 3) atomicAdd(&Y[m * ystride + n], acc[i][j]);
            else              Y[m * ystride + n] = acc[i][j];
        }
    }
}

// --------------------------- megakernel -----------------------------------
__global__ void __launch_bounds__(NTHR, 4)
mega_kernel(const float* __restrict__ img, const float* __restrict__ cloud,
            const float* __restrict__ img_tar, const float* __restrict__ cloud_tar,
            const float* __restrict__ cur_feat, const float* __restrict__ tgt_feat,
            const float* __restrict__ Wc1, const float* __restrict__ bc1,
            const float* __restrict__ Wc2, const float* __restrict__ bc2,
            const float* __restrict__ Wp1, const float* __restrict__ bp1,
            const float* __restrict__ Wp2, const float* __restrict__ bp2,
            const float* __restrict__ Wfc1, const float* __restrict__ bfc1,
            const float* __restrict__ Wfc2, const float* __restrict__ bfc2,
            const float* __restrict__ Wfu2, const float* __restrict__ bfu2,
            const float* __restrict__ Wpn1, const float* __restrict__ bpn1,
            const float* __restrict__ Wpn2, const float* __restrict__ bpn2,
            const float* __restrict__ Wpn3, const float* __restrict__ bpn3,
            float* __restrict__ out) {
    __shared__ Smem sm;
    int b = blockIdx.x;
    int tid = threadIdx.x;

    // ---- P0: KNN (0-187) || feat (188-251) || Weff fold x2 (252-347)
    //          || V fold (348-371) || beff (372-375) || bF (376)
    if (b < KNN_BLKS) {
        SmemKNN& k = sm.knn;
        for (int i = tid; i < N_PTS; i += NTHR) {
            float x = cloud[i * 3 + 0], y = cloud[i * 3 + 1], z = cloud[i * 3 + 2];
            k.x0[i] = x; k.y0[i] = y; k.z0[i] = z; k.w0[i] = x * x + y * y + z * z;
            x = cloud_tar[i * 3 + 0]; y = cloud_tar[i * 3 + 1]; z = cloud_tar[i * 3 + 2];
            k.x1[i] = x; k.y1[i] = y; k.z1[i] = z; k.w1[i] = x * x + y * y + z * z;
        }
        if (tid < 16) k.wsum[tid >> 3][tid & 7] = 0.0f;
        __syncthreads();
        int w = tid >> 5;
        int qid = b * 8 + w;
        if (qid < 1500) {
            int task = (qid < 500) ? 0 : (qid < 1000 ? 1 : 2);
            int q = qid - task * 500;
            if (task == 0) {
                float s = knn_one<K12, true>(k.x0, k.y0, k.z0, k.w0,
                                             k.x1[q], k.y1[q], k.z1[q],
                                             g_inds, g_wct, q);
                if ((tid & 31) == 0) k.wsum[0][w] = s;
            } else if (task == 1) {
                float s = knn_one<K12, true>(k.x1, k.y1, k.z1, k.w1,
                                             k.x1[q], k.y1[q], k.z1[q],
                                             g_inds_self, g_wcc, q);
                if ((tid & 31) == 0) k.wsum[1][w] = s;
            } else {
                knn_one<KPP, false>(k.x1, k.y1, k.z1, k.w1,
                                    k.x0[q], k.y0[q], k.z0[q],
                                    g_inds_pp, nullptr, q);
            }
        }
        __syncthreads();
        if (tid == 0) {
            float s0 = 0.0f, s1 = 0.0f;
#pragma unroll
            for (int i = 0; i < 8; i++) { s0 += k.wsum[0][i]; s1 += k.wsum[1][i]; }
            g_ws0[b] = s0; g_ws1[b] = s1;
        }
    } else if (b < 252) {
        int u = b - KNN_BLKS;
        int task = u >> 4, n0 = (u & 15) * 32;
        if (task == 0)      dev_feat<3, true>(n0, cloud_tar, Wp1, bp1, Wp2, bp2, g_cfT, sm);
        else if (task == 1) dev_feat<3, true>(n0, cloud, Wp1, bp1, Wp2, bp2, g_ctfT, sm);
        else if (task == 2) dev_feat<32, false>(n0, img_tar, Wc1, bc1, Wc2, bc2, g_icT, sm);
        else                dev_feat<32, false>(n0, img, Wc1, bc1, Wc2, bc2, g_itT, sm);
    } else if (b < 348) {
        int u = b - 252;  // 96 blocks: split-K x2 of Wpn2@Wpn1, 48 tiles each
        int half = u & 1, t = u >> 1;  // t: 0..47 = 16m x 3n
        gemm_tile<0, 2, 0, 0>(Wpn2 + half * 128, nullptr, 256, 128,
                              Wpn1 + half * 128 * 160, 160, (t % 3) * 64, 160,
                              g_Weffp + half * 1024 * 160, 160, 1024, 160,
                              (t / 3) * 64, (t % 3) * 64, sm);
    } else if (b < 372) {
        int u = b - 348;  // V fold: 2 halves x 3m x 4n, K=64 (exact-fit X)
        int v1 = (u >= 12) ? 1 : 0; int t = u - v1 * 12;
        gemm_tile<0, 2, 0, 1>(Wfu2 + v1 * 64, nullptr, 128, 64,
                              v1 ? Wfc1 : Wfc2, 256, (t % 4) * 64, 256,
                              g_V, 512, 160, 512,
                              (t / 4) * 64, (t % 4) * 64 + v1 * 256, sm);
    } else if (b < 376) {
        int base = (b - 372) * 256;
        for (int m = base + tid; m < base + 256; m += NTHR) {
            float a0 = 0.0f, a1 = 0.0f, a2 = 0.0f, a3 = 0.0f;
            const float* wr = Wpn2 + m * 256;
            for (int kk = 0; kk < 256; kk += 4) {
                a0 = fmaf(wr[kk], bpn1[kk], a0);
                a1 = fmaf(wr[kk + 1], bpn1[kk + 1], a1);
                a2 = fmaf(wr[kk + 2], bpn1[kk + 2], a2);
                a3 = fmaf(wr[kk + 3], bpn1[kk + 3], a3);
            }
            g_beff[m] = bpn2[m] + ((a0 + a1) + (a2 + a3));
        }
    } else if (b == 376) {
        if (tid < 160) {
            float a0 = 0.0f, a1 = 0.0f;
            const float* wr = Wfu2 + tid * 128;
            for (int kk = 0; kk < 64; kk++) {
                a0 = fmaf(wr[kk], bfc2[kk], a0);
                a1 = fmaf(wr[64 + kk], bfc1[kk], a1);
            }
            g_bF[tid] = bfu2[tid] + a0 + a1;
        }
    }
    gridbar<true>(0);  // payload: publishes g_inv[0..1]

    // ---- P1: pool1 (blocks 0-499) || init F = bF over stride-512 (500-511)
    if (b < 500) {
        float inv = g_inv[0];
        int half = tid >> 7, ch = tid & 127;
        int n = b;
        if (half == 0) {
            float mi = -CUDART_INF_F;
#pragma unroll
            for (int kk = 0; kk < K12; kk++) {
                int i = g_inds[n * K12 + kk];
                mi = fmaxf(mi, g_itT[i * 128 + ch] * (g_wct[n * K12 + kk] * inv));
            }
            g_cat[n * 512 + 256 + ch] = g_icT[n * 128 + ch] - mi;  // img_diff
        } else {
            float mp = -CUDART_INF_F;
#pragma unroll
            for (int kk = 0; kk < K12; kk++) {
                int i = g_inds[n * K12 + kk];
                mp = fmaxf(mp, g_ctfT[i * 128 + ch] * (g_wct[n * K12 + kk] * inv));
            }
            g_cat[n * 512 + ch] = g_cfT[n * 128 + ch] - mp;  // cloud_diff
        }
    } else {
        for (int e = (b - 500) * NTHR + tid; e < 160 * NSTR; e += 12 * NTHR)
            g_F[e] = g_bF[e >> 9];
    }
    gridbar<false>(1);

    // ---- P2: pool2 (blocks 0-249, 2 pts each) || P3a: F += V@catT over
    //          K-ranges [0,128)+[256,384) (cloud_diff/img_diff, final after P1)
    //          (blocks 250-441: 2 ranges x 4 splits x 24 tiles)
    if (b < 250) {
        float inv = g_inv[1];
        int sub = tid >> 7, ch = tid & 127;
        int n = b * 2 + sub;
        float mspd = -CUDART_INF_F, msid = -CUDART_INF_F;
#pragma unroll
        for (int kk = 0; kk < K12; kk++) {
            int i = g_inds_self[n * K12 + kk];
            float w = g_wcc[n * K12 + kk] * inv;
            mspd = fmaxf(mspd, g_cat[i * 512 + ch] * w);        // cloud_diff
            msid = fmaxf(msid, g_cat[i * 512 + 256 + ch] * w);  // img_diff
        }
        g_cat[n * 512 + 384 + ch] = mspd;  // spd
        g_cat[n * 512 + 128 + ch] = msid;  // sid
    } else if (b < 442) {
        int u = b - 250;
        int r = u & 1, slab = (u >> 1) & 3, t = u >> 3;  // t: 0..23 = 3m x 8n
        int kb = r * 256 + slab * 32;
        gemm_tile<1, 3, 0, 0>(g_V + kb, nullptr, 512, 32,
                              g_cat + kb, 512, (t & 7) * 64, 512,
                              g_F, NSTR, 160, 512, (t >> 3) * 64, (t & 7) * 64, sm);
    }
    gridbar<false>(2);

    // ---- P3b: F += V@catT over K-ranges [128,256)+[384,512) (sid/spd)
    //           (blocks 0-191) || init X2 = beff, X3 = bpn3 (blocks 192-511)
    if (b < 192) {
        int r = b & 1, slab = (b >> 1) & 3, t = b >> 3;  // t: 0..23 = 3m x 8n
        int kb = 128 + r * 256 + slab * 32;
        gemm_tile<1, 3, 0, 0>(g_V + kb, nullptr, 512, 32,
                              g_cat + kb, 512, (t & 7) * 64, 512,
                              g_F, NSTR, 160, 512, (t >> 3) * 64, (t & 7) * 64, sm);
    } else {
        int u = b - 192;  // 320 blocks
        for (int e = u * NTHR + tid; e < 1024 * NSTR; e += 320 * NTHR)
            g_X2[e] = g_beff[e >> 9];
        for (int e = u * NTHR + tid; e < 160 * NSTR; e += 320 * NTHR)
            g_X3[e] = bpn3[e >> 9];
    }
    gridbar<false>(3);

    // ---- P4: X2 += (Weffp0+Weffp1) @ F  (split-K x2, blocks 0-255)
    if (b < 256) {
        int half = b & 1, t = b >> 1;  // t: 0..127 = 16m x 8n
        gemm_tile<0, 3, 1, 1>(g_Weffp + half * 80, g_Weffp + 1024 * 160 + half * 80,
                              160, 80,
                              g_F + half * 80 * NSTR, NSTR, (t & 7) * 64, 512,
                              g_X2, NSTR, 1024, 512, (t >> 3) * 64, (t & 7) * 64, sm);
    }
    gridbar<false>(4);

    // ---- P5: X3 += Wpn3 @ lrelu(X2)  (split-K x8, blocks 0-191)
    if (b < 192) {
        int slab = b & 7, t = b >> 3;  // t: 0..23 = 3m x 8n
        gemm_tile<2, 3, 0, 1>(Wpn3 + slab * 128, nullptr, 1024, 128,
                              g_X2 + slab * 128 * NSTR, NSTR, (t & 7) * 64, 512,
                              g_X3, NSTR, 160, 512, (t >> 3) * 64, (t & 7) * 64, sm);
    }
    gridbar<false>(5);

    // ---- P6: final gather-mean (blocks 0-499)
    if (b < 500 && tid < 160) {
        int n = b;
        float s = 0.0f;
#pragma unroll
        for (int kk = 0; kk < KPP; kk++) {
            int i = g_inds_pp[n * KPP + kk];
            s += tgt_feat[tid * N_PTS + i] * g_X3[tid * NSTR + i];
        }
        out[tid * N_PTS + n] = cur_feat[tid * N_PTS + n] + 0.25f * s;
    }
}

// --------------------------------------------------------------------------
extern "C" void kernel_launch(void* const* d_in, const int* in_sizes, int n_in,
                              void* d_out, int out_size) {
    mega_kernel<<<NBLK, NTHR>>>(
        (const float*)d_in[0],  (const float*)d_in[1],
        (const float*)d_in[2],  (const float*)d_in[3],
        (const float*)d_in[4],  (const float*)d_in[5],
        (const float*)d_in[6],  (const float*)d_in[7],
        (const float*)d_in[8],  (const float*)d_in[9],
        (const float*)d_in[10], (const float*)d_in[11],
        (const float*)d_in[12], (const float*)d_in[13],
        (const float*)d_in[14], (const float*)d_in[15],
        (const float*)d_in[16], (const float*)d_in[17],
        (const float*)d_in[18], (const float*)d_in[19],
        (const float*)d_in[20], (const float*)d_in[21],
        (const float*)d_in[22], (const float*)d_in[23],
        (const float*)d_in[24], (const float*)d_in[25],
        (float*)d_out);
}

// round 15
// speedup vs baseline: 1.0590x; 1.0203x over previous
#include <cuda_runtime.h>
#include <math_constants.h>

#define N_PTS 500
#define NSTR 512
#define K12 12
#define KPP 4
#define NBLK 512
#define NTHR 256
#define KNN_BLKS 188

// ---------------- scratch (device globals; no allocation) ----------------
__device__ float g_cfT[N_PTS * 128];
__device__ float g_ctfT[N_PTS * 128];
__device__ float g_icT[N_PTS * 128];
__device__ float g_itT[N_PTS * 128];
__device__ int   g_inds[N_PTS * K12];
__device__ int   g_inds_self[N_PTS * K12];
__device__ int   g_inds_pp[N_PTS * KPP];
__device__ float g_wct[N_PTS * K12];
__device__ float g_wcc[N_PTS * K12];
__device__ float g_ws0[192];
__device__ float g_ws1[192];
__device__ float g_inv[2];
__device__ float g_cat[NSTR * 512];       // padded rows 500-511 stay 0 (zero-init)
__device__ float g_V[160 * 512];          // folded fuse2@fc weights
__device__ float g_bF[160];
__device__ float g_Weffp[2 * 1024 * 160]; // split-K partials of Wpn2@Wpn1
__device__ float g_beff[1024];
__device__ float g_F[160 * NSTR];         // init bF, RED-accumulated (stride 512)
__device__ float g_X2[1024 * NSTR];       // init beff, RED-accumulated
__device__ float g_X3[160 * NSTR];        // init bpn3, RED-accumulated

// ---------------- flag-based grid barrier (tight spin, replay-safe) -------
__device__ unsigned g_flag[8][NBLK];
__device__ unsigned g_bar_gen[8];
__device__ unsigned g_cnt[8];             // X2 128-row-block completion counters

template <bool PAYLOAD>
__device__ __forceinline__ void gridbar(int slot) {
    __shared__ float s_red[2][8];
    __syncthreads();
    if (blockIdx.x == 0) {
        if (threadIdx.x == 0) {
            __threadfence();
            unsigned gen = *(volatile unsigned*)&g_bar_gen[slot];
            *(volatile unsigned*)&g_flag[slot][0] = gen + 1;
        }
        __syncthreads();
        unsigned gen = *(volatile unsigned*)&g_bar_gen[slot];
        for (int j = threadIdx.x; j < NBLK; j += NTHR)
            while (*(volatile unsigned*)&g_flag[slot][j] != gen + 1) {}
        __syncthreads();
        if (PAYLOAD) {
            int t = threadIdx.x;
            float v0 = (t < 192) ? g_ws0[t] : 0.0f;
            float v1 = (t < 192) ? g_ws1[t] : 0.0f;
#pragma unroll
            for (int off = 16; off > 0; off >>= 1) {
                v0 += __shfl_down_sync(0xffffffffu, v0, off);
                v1 += __shfl_down_sync(0xffffffffu, v1, off);
            }
            if ((t & 31) == 0) { s_red[0][t >> 5] = v0; s_red[1][t >> 5] = v1; }
            __syncthreads();
            if (t == 0) {
                float s0 = 0.0f, s1 = 0.0f;
#pragma unroll
                for (int i = 0; i < 8; i++) { s0 += s_red[0][i]; s1 += s_red[1][i]; }
                g_inv[0] = 1.0f / s0;
                g_inv[1] = 1.0f / s1;
            }
            __syncthreads();
        }
        if (threadIdx.x == 0) {
            __threadfence();
            *(volatile unsigned*)&g_bar_gen[slot] =
                *(volatile unsigned*)&g_bar_gen[slot] + 1;
        }
        __syncthreads();
    } else {
        if (threadIdx.x == 0) {
            __threadfence();
            unsigned gen = *(volatile unsigned*)&g_bar_gen[slot];
            *(volatile unsigned*)&g_flag[slot][blockIdx.x] = gen + 1;
            while (*(volatile unsigned*)&g_bar_gen[slot] == gen) {}
        }
        __syncthreads();
    }
}

// ---------------- shared memory union -------------------------------------
struct SmemKNN {
    float x0[N_PTS], y0[N_PTS], z0[N_PTS], w0[N_PTS];
    float x1[N_PTS], y1[N_PTS], z1[N_PTS], w1[N_PTS];
    float wsum[2][8];
};
struct SmemFeat { float W2s[128 * 64]; float xin[32 * 32]; float hid[64 * 32]; };
struct SmemGemm { float Ws[2][16][68]; float Xs[2][16][68]; };
union __align__(16) Smem {
    SmemKNN knn;
    SmemFeat feat;
    SmemGemm gemm;
};

// ---------------- warp-cooperative KNN ------------------------------------
template <int K, bool WCALC>
__device__ float knn_one(const float* __restrict__ rx, const float* __restrict__ ry,
                         const float* __restrict__ rz, const float* __restrict__ rr,
                         float qx, float qy, float qz,
                         int* __restrict__ outIdx, float* __restrict__ wOut, int q) {
    int lane = threadIdx.x & 31;
    float qq = qx * qx + qy * qy + qz * qz;
    float dist[K]; int idx[K];
#pragma unroll
    for (int t = 0; t < K; t++) { dist[t] = CUDART_INF_F; idx[t] = 0x7fffffff; }
    for (int r = lane; r < N_PTS; r += 32) {
        float d2 = qq - 2.0f * (qx * rx[r] + qy * ry[r] + qz * rz[r]) + rr[r];
        if (d2 < dist[K - 1]) {
            dist[K - 1] = d2; idx[K - 1] = r;
#pragma unroll
            for (int t = K - 1; t > 0; --t) {
                if (dist[t] < dist[t - 1]) {
                    float td = dist[t]; dist[t] = dist[t - 1]; dist[t - 1] = td;
                    int ti = idx[t]; idx[t] = idx[t - 1]; idx[t - 1] = ti;
                }
            }
        }
    }
    int mywin = 0;
#pragma unroll
    for (int t = 0; t < K; t++) {
        float bd = dist[0]; int bi = idx[0];
#pragma unroll
        for (int off = 16; off > 0; off >>= 1) {
            float od = __shfl_down_sync(0xffffffffu, bd, off);
            int oi = __shfl_down_sync(0xffffffffu, bi, off);
            if (od < bd || (od == bd && oi < bi)) { bd = od; bi = oi; }
        }
        bi = __shfl_sync(0xffffffffu, bi, 0);
        if (lane == 0) outIdx[q * K + t] = bi;
        if (lane == t) mywin = bi;
        if (idx[0] == bi) {
#pragma unroll
            for (int tt = 0; tt < K - 1; tt++) { dist[tt] = dist[tt + 1]; idx[tt] = idx[tt + 1]; }
            dist[K - 1] = CUDART_INF_F; idx[K - 1] = 0x7fffffff;
        }
    }
    float e = 0.0f;
    if (WCALC) {
        if (lane < K) {
            float dx = qx - rx[mywin], dy = qy - ry[mywin], dz = qz - rz[mywin];
            float d = sqrtf(dx * dx + dy * dy + dz * dz + 1e-12f);
            e = expf(-d);
            wOut[q * K + lane] = e;
        }
#pragma unroll
        for (int off = 16; off > 0; off >>= 1)
            e += __shfl_down_sync(0xffffffffu, e, off);
    }
    return e;
}

// ---------------- feature tile (2-layer 1x1 conv), point-major out --------
template <int IN_CH, bool CLOUD>
__device__ void dev_feat(int n0, const float* __restrict__ src,
                         const float* __restrict__ W1, const float* __restrict__ b1,
                         const float* __restrict__ W2, const float* __restrict__ b2,
                         float* __restrict__ out, Smem& sm) {
    int tid = threadIdx.x;
    if (CLOUD) {
        for (int i = tid; i < IN_CH * 32; i += NTHR) {
            int c = i >> 5, p = i & 31;
            sm.feat.xin[i] = (n0 + p < N_PTS) ? src[(n0 + p) * 3 + c] : 0.0f;
        }
    } else {
        for (int i = tid; i < IN_CH * 32; i += NTHR) {
            int c = i >> 5, p = i & 31;
            sm.feat.xin[i] = (n0 + p < N_PTS) ? src[c * N_PTS + n0 + p] : 0.0f;
        }
    }
    for (int i = tid; i < 128 * 64 / 4; i += NTHR)
        ((float4*)sm.feat.W2s)[i] = ((const float4*)W2)[i];
    __syncthreads();

    int pt = tid & 31, g = tid >> 5;
#pragma unroll
    for (int cc = 0; cc < 8; cc++) {
        int ch = g * 8 + cc;
        float h = b1[ch];
#pragma unroll
        for (int i = 0; i < IN_CH; i++)
            h = fmaf(W1[ch * IN_CH + i], sm.feat.xin[i * 32 + pt], h);
        sm.feat.hid[ch * 32 + pt] = (h > 0.0f) ? h : 0.01f * h;
    }
    __syncthreads();

    int ch0 = g * 16;
    float acc[16];
#pragma unroll
    for (int i = 0; i < 16; i++) acc[i] = b2[ch0 + i];
#pragma unroll 4
    for (int j = 0; j < 64; j++) {
        float h = sm.feat.hid[j * 32 + pt];
#pragma unroll
        for (int i = 0; i < 16; i++)
            acc[i] = fmaf(sm.feat.W2s[(ch0 + i) * 64 + j], h, acc[i]);
    }
    int n = n0 + pt;
    if (n < N_PTS) {
#pragma unroll
        for (int i = 0; i < 16; i++) out[n * 128 + ch0 + i] = acc[i];
    }
    __syncthreads();
}

// ---------------- double-buffered 64x64 GEMM tile -------------------------
// XMODE: 0 plain X[k*xstride+col]; 1 xT X[col*xstride+k]; 2 lrelu(plain)
// OUTMODE: 2 store raw; 3 atomicAdd(RED) raw.  WSUM: W = Wa + Wb
// PADX: X buffer padded -> unguarded float4 loads (XMODE 0/2 only)
template <int XMODE, int OUTMODE, int WSUM, int PADX>
__device__ void gemm_tile(const float* __restrict__ Wa, const float* __restrict__ Wb,
                          int KW, int kLen,
                          const float* __restrict__ X, int xstride, int xn0, int Nx,
                          float* __restrict__ Y, int ystride,
                          int M, int Nout, int m0, int n0, Smem& sm) {
    int tid = threadIdx.x;
    int ty = tid >> 4, tx = tid & 15;
    float acc[4][4] = {};
    float4 pw, px4;
    float pxs[4];
    int wrow = (tid * 4) >> 4, wcol = (tid * 4) & 15;
    int xkr = tid >> 4, xc4 = (tid & 15) * 4;

    auto loadW = [&](int k0) {
        if (m0 + wrow < M) {
            pw = *(const float4*)&Wa[(m0 + wrow) * KW + k0 + wcol];
            if (WSUM) {
                float4 w2 = *(const float4*)&Wb[(m0 + wrow) * KW + k0 + wcol];
                pw.x += w2.x; pw.y += w2.y; pw.z += w2.z; pw.w += w2.w;
            }
        } else {
            pw = make_float4(0.f, 0.f, 0.f, 0.f);
        }
    };
    auto loadX = [&](int k0) {
        if (XMODE == 1) {
#pragma unroll
            for (int i = 0; i < 4; i++) {
                int l = tid + i * NTHR;
                int kr = l & 15, col = l >> 4;
                pxs[i] = (xn0 + col < Nx) ? X[(xn0 + col) * xstride + k0 + kr] : 0.0f;
            }
        } else if (PADX) {
            px4 = *(const float4*)&X[(k0 + xkr) * xstride + xn0 + xc4];
            if (XMODE == 2) {
                px4.x = (px4.x > 0.0f) ? px4.x : 0.01f * px4.x;
                px4.y = (px4.y > 0.0f) ? px4.y : 0.01f * px4.y;
                px4.z = (px4.z > 0.0f) ? px4.z : 0.01f * px4.z;
                px4.w = (px4.w > 0.0f) ? px4.w : 0.01f * px4.w;
            }
        } else {
            const float* row = &X[(k0 + xkr) * xstride + xn0];
            px4.x = (xn0 + xc4 + 0 < Nx) ? row[xc4 + 0] : 0.0f;
            px4.y = (xn0 + xc4 + 1 < Nx) ? row[xc4 + 1] : 0.0f;
            px4.z = (xn0 + xc4 + 2 < Nx) ? row[xc4 + 2] : 0.0f;
            px4.w = (xn0 + xc4 + 3 < Nx) ? row[xc4 + 3] : 0.0f;
            if (XMODE == 2) {
                px4.x = (px4.x > 0.0f) ? px4.x : 0.01f * px4.x;
                px4.y = (px4.y > 0.0f) ? px4.y : 0.01f * px4.y;
                px4.z = (px4.z > 0.0f) ? px4.z : 0.01f * px4.z;
                px4.w = (px4.w > 0.0f) ? px4.w : 0.01f * px4.w;
            }
        }
    };

    loadW(0); loadX(0);
    int p = 0;
    for (int k0 = 0; k0 < kLen; k0 += 16) {
        sm.gemm.Ws[p][wcol + 0][wrow] = pw.x;
        sm.gemm.Ws[p][wcol + 1][wrow] = pw.y;
        sm.gemm.Ws[p][wcol + 2][wrow] = pw.z;
        sm.gemm.Ws[p][wcol + 3][wrow] = pw.w;
        if (XMODE == 1) {
#pragma unroll
            for (int i = 0; i < 4; i++) {
                int l = tid + i * NTHR;
                sm.gemm.Xs[p][l & 15][l >> 4] = pxs[i];
            }
        } else {
            *(float4*)&sm.gemm.Xs[p][xkr][xc4] = px4;
        }
        __syncthreads();
        if (k0 + 16 < kLen) { loadW(k0 + 16); loadX(k0 + 16); }
#pragma unroll
        for (int kk = 0; kk < 16; kk++) {
            float4 a4 = *(const float4*)&sm.gemm.Ws[p][kk][ty * 4];
            float4 b4 = *(const float4*)&sm.gemm.Xs[p][kk][tx * 4];
            float a[4] = {a4.x, a4.y, a4.z, a4.w};
            float bb[4] = {b4.x, b4.y, b4.z, b4.w};
#pragma unroll
            for (int i = 0; i < 4; i++)
#pragma unroll
                for (int j = 0; j < 4; j++)
                    acc[i][j] = fmaf(a[i], bb[j], acc[i][j]);
        }
        p ^= 1;
    }
#pragma unroll
    for (int i = 0; i < 4; i++) {
        int m = m0 + ty * 4 + i;
        if (m >= M) continue;
#pragma unroll
        for (int j = 0; j < 4; j++) {
            int n = n0 + tx * 4 + j;
            if (n >= Nout) continue;
            if (OUTMODE == 3) atomicAdd(&Y[m * ystride + n], acc[i][j]);
            else              Y[m * ystride + n] = acc[i][j];
        }
    }
}

// --------------------------- megakernel -----------------------------------
__global__ void __launch_bounds__(NTHR, 4)
mega_kernel(const float* __restrict__ img, const float* __restrict__ cloud,
            const float* __restrict__ img_tar, const float* __restrict__ cloud_tar,
            const float* __restrict__ cur_feat, const float* __restrict__ tgt_feat,
            const float* __restrict__ Wc1, const float* __restrict__ bc1,
            const float* __restrict__ Wc2, const float* __restrict__ bc2,
            const float* __restrict__ Wp1, const float* __restrict__ bp1,
            const float* __restrict__ Wp2, const float* __restrict__ bp2,
            const float* __restrict__ Wfc1, const float* __restrict__ bfc1,
            const float* __restrict__ Wfc2, const float* __restrict__ bfc2,
            const float* __restrict__ Wfu2, const float* __restrict__ bfu2,
            const float* __restrict__ Wpn1, const float* __restrict__ bpn1,
            const float* __restrict__ Wpn2, const float* __restrict__ bpn2,
            const float* __restrict__ Wpn3, const float* __restrict__ bpn3,
            float* __restrict__ out) {
    __shared__ Smem sm;
    int b = blockIdx.x;
    int tid = threadIdx.x;

    // ---- P0: KNN (0-187) || feat (188-251) || Weff fold x2 (252-347)
    //          || V fold (348-371) || beff (372-375) || bF + cnt reset (376)
    if (b < KNN_BLKS) {
        SmemKNN& k = sm.knn;
        for (int i = tid; i < N_PTS; i += NTHR) {
            float x = cloud[i * 3 + 0], y = cloud[i * 3 + 1], z = cloud[i * 3 + 2];
            k.x0[i] = x; k.y0[i] = y; k.z0[i] = z; k.w0[i] = x * x + y * y + z * z;
            x = cloud_tar[i * 3 + 0]; y = cloud_tar[i * 3 + 1]; z = cloud_tar[i * 3 + 2];
            k.x1[i] = x; k.y1[i] = y; k.z1[i] = z; k.w1[i] = x * x + y * y + z * z;
        }
        if (tid < 16) k.wsum[tid >> 3][tid & 7] = 0.0f;
        __syncthreads();
        int w = tid >> 5;
        int qid = b * 8 + w;
        if (qid < 1500) {
            int task = (qid < 500) ? 0 : (qid < 1000 ? 1 : 2);
            int q = qid - task * 500;
            if (task == 0) {
                float s = knn_one<K12, true>(k.x0, k.y0, k.z0, k.w0,
                                             k.x1[q], k.y1[q], k.z1[q],
                                             g_inds, g_wct, q);
                if ((tid & 31) == 0) k.wsum[0][w] = s;
            } else if (task == 1) {
                float s = knn_one<K12, true>(k.x1, k.y1, k.z1, k.w1,
                                             k.x1[q], k.y1[q], k.z1[q],
                                             g_inds_self, g_wcc, q);
                if ((tid & 31) == 0) k.wsum[1][w] = s;
            } else {
                knn_one<KPP, false>(k.x1, k.y1, k.z1, k.w1,
                                    k.x0[q], k.y0[q], k.z0[q],
                                    g_inds_pp, nullptr, q);
            }
        }
        __syncthreads();
        if (tid == 0) {
            float s0 = 0.0f, s1 = 0.0f;
#pragma unroll
            for (int i = 0; i < 8; i++) { s0 += k.wsum[0][i]; s1 += k.wsum[1][i]; }
            g_ws0[b] = s0; g_ws1[b] = s1;
        }
    } else if (b < 252) {
        int u = b - KNN_BLKS;
        int task = u >> 4, n0 = (u & 15) * 32;
        if (task == 0)      dev_feat<3, true>(n0, cloud_tar, Wp1, bp1, Wp2, bp2, g_cfT, sm);
        else if (task == 1) dev_feat<3, true>(n0, cloud, Wp1, bp1, Wp2, bp2, g_ctfT, sm);
        else if (task == 2) dev_feat<32, false>(n0, img_tar, Wc1, bc1, Wc2, bc2, g_icT, sm);
        else                dev_feat<32, false>(n0, img, Wc1, bc1, Wc2, bc2, g_itT, sm);
    } else if (b < 348) {
        int u = b - 252;  // 96 blocks: split-K x2 of Wpn2@Wpn1, 48 tiles each
        int half = u & 1, t = u >> 1;  // t: 0..47 = 16m x 3n
        gemm_tile<0, 2, 0, 0>(Wpn2 + half * 128, nullptr, 256, 128,
                              Wpn1 + half * 128 * 160, 160, (t % 3) * 64, 160,
                              g_Weffp + half * 1024 * 160, 160, 1024, 160,
                              (t / 3) * 64, (t % 3) * 64, sm);
    } else if (b < 372) {
        int u = b - 348;  // V fold: 2 halves x 3m x 4n, K=64 (exact-fit X)
        int v1 = (u >= 12) ? 1 : 0; int t = u - v1 * 12;
        gemm_tile<0, 2, 0, 1>(Wfu2 + v1 * 64, nullptr, 128, 64,
                              v1 ? Wfc1 : Wfc2, 256, (t % 4) * 64, 256,
                              g_V, 512, 160, 512,
                              (t / 4) * 64, (t % 4) * 64 + v1 * 256, sm);
    } else if (b < 376) {
        int base = (b - 372) * 256;
        for (int m = base + tid; m < base + 256; m += NTHR) {
            float a0 = 0.0f, a1 = 0.0f, a2 = 0.0f, a3 = 0.0f;
            const float* wr = Wpn2 + m * 256;
            for (int kk = 0; kk < 256; kk += 4) {
                a0 = fmaf(wr[kk], bpn1[kk], a0);
                a1 = fmaf(wr[kk + 1], bpn1[kk + 1], a1);
                a2 = fmaf(wr[kk + 2], bpn1[kk + 2], a2);
                a3 = fmaf(wr[kk + 3], bpn1[kk + 3], a3);
            }
            g_beff[m] = bpn2[m] + ((a0 + a1) + (a2 + a3));
        }
    } else if (b == 376) {
        if (tid < 160) {
            float a0 = 0.0f, a1 = 0.0f;
            const float* wr = Wfu2 + tid * 128;
            for (int kk = 0; kk < 64; kk++) {
                a0 = fmaf(wr[kk], bfc2[kk], a0);
                a1 = fmaf(wr[64 + kk], bfc1[kk], a1);
            }
            g_bF[tid] = bfu2[tid] + a0 + a1;
        }
        if (tid < 8) g_cnt[tid] = 0u;  // replay-safe reset (ordered by bar0..3)
    }
    gridbar<true>(0);  // payload: publishes g_inv[0..1]

    // ---- P1: pool1 (blocks 0-499) || init F = bF over stride-512 (500-511)
    if (b < 500) {
        float inv = g_inv[0];
        int half = tid >> 7, ch = tid & 127;
        int n = b;
        if (half == 0) {
            float mi = -CUDART_INF_F;
#pragma unroll
            for (int kk = 0; kk < K12; kk++) {
                int i = g_inds[n * K12 + kk];
                mi = fmaxf(mi, g_itT[i * 128 + ch] * (g_wct[n * K12 + kk] * g_inv[0]));
            }
            g_cat[n * 512 + 256 + ch] = g_icT[n * 128 + ch] - mi;  // img_diff
        } else {
            float mp = -CUDART_INF_F;
#pragma unroll
            for (int kk = 0; kk < K12; kk++) {
                int i = g_inds[n * K12 + kk];
                mp = fmaxf(mp, g_ctfT[i * 128 + ch] * (g_wct[n * K12 + kk] * inv));
            }
            g_cat[n * 512 + ch] = g_cfT[n * 128 + ch] - mp;  // cloud_diff
        }
    } else {
        for (int e = (b - 500) * NTHR + tid; e < 160 * NSTR; e += 12 * NTHR)
            g_F[e] = g_bF[e >> 9];
    }
    gridbar<false>(1);

    // ---- P2: pool2 (blocks 0-249, 2 pts each) || P3a: F += V@catT over
    //          K-ranges [0,128)+[256,384) (blocks 250-441)
    if (b < 250) {
        float inv = g_inv[1];
        int sub = tid >> 7, ch = tid & 127;
        int n = b * 2 + sub;
        float mspd = -CUDART_INF_F, msid = -CUDART_INF_F;
#pragma unroll
        for (int kk = 0; kk < K12; kk++) {
            int i = g_inds_self[n * K12 + kk];
            float w = g_wcc[n * K12 + kk] * inv;
            mspd = fmaxf(mspd, g_cat[i * 512 + ch] * w);        // cloud_diff
            msid = fmaxf(msid, g_cat[i * 512 + 256 + ch] * w);  // img_diff
        }
        g_cat[n * 512 + 384 + ch] = mspd;  // spd
        g_cat[n * 512 + 128 + ch] = msid;  // sid
    } else if (b < 442) {
        int u = b - 250;
        int r = u & 1, slab = (u >> 1) & 3, t = u >> 3;  // t: 0..23 = 3m x 8n
        int kb = r * 256 + slab * 32;
        gemm_tile<1, 3, 0, 0>(g_V + kb, nullptr, 512, 32,
                              g_cat + kb, 512, (t & 7) * 64, 512,
                              g_F, NSTR, 160, 512, (t >> 3) * 64, (t & 7) * 64, sm);
    }
    gridbar<false>(2);

    // ---- P3b: F += V@catT over K-ranges [128,256)+[384,512) (blocks 0-191)
    //           || init X2 = beff, X3 = bpn3 (blocks 192-511)
    if (b < 192) {
        int r = b & 1, slab = (b >> 1) & 3, t = b >> 3;  // t: 0..23 = 3m x 8n
        int kb = 128 + r * 256 + slab * 32;
        gemm_tile<1, 3, 0, 0>(g_V + kb, nullptr, 512, 32,
                              g_cat + kb, 512, (t & 7) * 64, 512,
                              g_F, NSTR, 160, 512, (t >> 3) * 64, (t & 7) * 64, sm);
    } else {
        int u = b - 192;  // 320 blocks
        for (int e = u * NTHR + tid; e < 1024 * NSTR; e += 320 * NTHR)
            g_X2[e] = g_beff[e >> 9];
        for (int e = u * NTHR + tid; e < 160 * NSTR; e += 320 * NTHR)
            g_X3[e] = bpn3[e >> 9];
    }
    gridbar<false>(3);

    // ---- P4: X2 += (Weffp0+Weffp1) @ F  (split-K x2, blocks 0-255),
    //          each tile signals its 128-row X2 block counter on completion.
    if (b < 256) {
        int half = b & 1, t = b >> 1;  // t: 0..127 = 16m x 8n
        gemm_tile<0, 3, 1, 1>(g_Weffp + half * 80, g_Weffp + 1024 * 160 + half * 80,
                              160, 80,
                              g_F + half * 80 * NSTR, NSTR, (t & 7) * 64, 512,
                              g_X2, NSTR, 1024, 512, (t >> 3) * 64, (t & 7) * 64, sm);
        __threadfence();
        __syncthreads();
        if (tid == 0) atomicAdd(&g_cnt[t >> 4], 1u);  // rowblock = m0/128
    }
    // (no grid barrier: P5 consumes via per-rowblock counters)

    // ---- P5: X3 += Wpn3 @ lrelu(X2)  (split-K x8, blocks 0-191), gated on
    //          its X2 rowblock being complete (32 tile-completions).
    if (b < 192) {
        int slab = b & 7, t = b >> 3;  // t: 0..23 = 3m x 8n
        if (tid == 0) {
            while (*(volatile unsigned*)&g_cnt[slab] < 32u) {}
            __threadfence();
        }
        __syncthreads();
        gemm_tile<2, 3, 0, 1>(Wpn3 + slab * 128, nullptr, 1024, 128,
                              g_X2 + slab * 128 * NSTR, NSTR, (t & 7) * 64, 512,
                              g_X3, NSTR, 160, 512, (t >> 3) * 64, (t & 7) * 64, sm);
    }
    gridbar<false>(5);

    // ---- P6: final gather-mean (blocks 0-499)
    if (b < 500 && tid < 160) {
        int n = b;
        float s = 0.0f;
#pragma unroll
        for (int kk = 0; kk < KPP; kk++) {
            int i = g_inds_pp[n * KPP + kk];
            s += tgt_feat[tid * N_PTS + i] * g_X3[tid * NSTR + i];
        }
        out[tid * N_PTS + n] = cur_feat[tid * N_PTS + n] + 0.25f * s;
    }
}

// --------------------------------------------------------------------------
extern "C" void kernel_launch(void* const* d_in, const int* in_sizes, int n_in,
                              void* d_out, int out_size) {
    mega_kernel<<<NBLK, NTHR>>>(
        (const float*)d_in[0],  (const float*)d_in[1],
        (const float*)d_in[2],  (const float*)d_in[3],
        (const float*)d_in[4],  (const float*)d_in[5],
        (const float*)d_in[6],  (const float*)d_in[7],
        (const float*)d_in[8],  (const float*)d_in[9],
        (const float*)d_in[10], (const float*)d_in[11],
        (const float*)d_in[12], (const float*)d_in[13],
        (const float*)d_in[14], (const float*)d_in[15],
        (const float*)d_in[16], (const float*)d_in[17],
        (const float*)d_in[18], (const float*)d_in[19],
        (const float*)d_in[20], (const float*)d_in[21],
        (const float*)d_in[22], (const float*)d_in[23],
        (const float*)d_in[24], (const float*)d_in[25],
        (float*)d_out);
}

// round 16
// speedup vs baseline: 1.1297x; 1.0667x over previous
#include <cuda_runtime.h>
#include <math_constants.h>

#define N_PTS 500
#define NSTR 512
#define K12 12
#define KPP 4
#define NBLK 512
#define NTHR 256
#define KNN_BLKS 188
#define WEFF_STR (1024 * 160)

// ---------------- scratch (device globals; no allocation) ----------------
__device__ float g_cfT[N_PTS * 128];
__device__ float g_ctfT[N_PTS * 128];
__device__ float g_icT[N_PTS * 128];
__device__ float g_itT[N_PTS * 128];
__device__ int   g_inds[N_PTS * K12];
__device__ int   g_inds_self[N_PTS * K12];
__device__ int   g_inds_pp[N_PTS * KPP];
__device__ float g_wct[N_PTS * K12];
__device__ float g_wcc[N_PTS * K12];
__device__ float g_ws0[192];
__device__ float g_ws1[192];
__device__ float g_cat[NSTR * 512];       // padded rows 500-511 stay 0 (zero-init)
__device__ float g_V[160 * 512];          // folded fuse2@fc weights
__device__ float g_bF[160];
__device__ float g_Weffp[4 * WEFF_STR];   // split-K x4 partials of Wpn2@Wpn1
__device__ float g_beff[1024];
__device__ float g_F[160 * NSTR];         // init bF, RED-accumulated (stride 512)
__device__ float g_X2[1024 * NSTR];       // init beff, RED-accumulated
__device__ float g_X3[160 * NSTR];        // init bpn3, RED-accumulated

// ---------------- masterless monotonic counter barrier (replay-safe) ------
__device__ unsigned g_count[8];
__device__ unsigned g_cnt[8];             // X2 128-row-block completion counters

__device__ __forceinline__ void gridbar(int slot) {
    __syncthreads();
    if (threadIdx.x == 0) {
        __threadfence();
        unsigned old = atomicAdd(&g_count[slot], 1u) + 1u;
        unsigned target = ((old + NBLK - 1u) / NBLK) * NBLK;
        while (*(volatile unsigned*)&g_count[slot] < target) {}
        __threadfence();
    }
    __syncthreads();
}

// ---------------- shared memory union -------------------------------------
struct SmemKNN {
    float x0[N_PTS], y0[N_PTS], z0[N_PTS], w0[N_PTS];
    float x1[N_PTS], y1[N_PTS], z1[N_PTS], w1[N_PTS];
    float wsum[2][8];
};
struct SmemFeat { float W2s[128 * 64]; float xin[32 * 32]; float hid[64 * 32]; };
struct SmemGemm { float Ws[2][16][68]; float Xs[2][16][68]; };
struct SmemPool { float red[8]; float inv; };
union __align__(16) Smem {
    SmemKNN knn;
    SmemFeat feat;
    SmemGemm gemm;
    SmemPool pool;
};

// deterministic per-block softmax-denominator reduction (identical all blocks)
__device__ float block_inv(const float* __restrict__ arr, Smem& sm) {
    int tid = threadIdx.x;
    float v = (tid < KNN_BLKS) ? arr[tid] : 0.0f;
#pragma unroll
    for (int off = 16; off > 0; off >>= 1)
        v += __shfl_down_sync(0xffffffffu, v, off);
    if ((tid & 31) == 0) sm.pool.red[tid >> 5] = v;
    __syncthreads();
    if (tid == 0) {
        float s = 0.0f;
#pragma unroll
        for (int i = 0; i < 8; i++) s += sm.pool.red[i];
        sm.pool.inv = 1.0f / s;
    }
    __syncthreads();
    return sm.pool.inv;
}

// ---------------- warp-cooperative KNN ------------------------------------
template <int K, bool WCALC>
__device__ float knn_one(const float* __restrict__ rx, const float* __restrict__ ry,
                         const float* __restrict__ rz, const float* __restrict__ rr,
                         float qx, float qy, float qz,
                         int* __restrict__ outIdx, float* __restrict__ wOut, int q) {
    int lane = threadIdx.x & 31;
    float qq = qx * qx + qy * qy + qz * qz;
    float dist[K]; int idx[K];
#pragma unroll
    for (int t = 0; t < K; t++) { dist[t] = CUDART_INF_F; idx[t] = 0x7fffffff; }
    for (int r = lane; r < N_PTS; r += 32) {
        float d2 = qq - 2.0f * (qx * rx[r] + qy * ry[r] + qz * rz[r]) + rr[r];
        if (d2 < dist[K - 1]) {
            dist[K - 1] = d2; idx[K - 1] = r;
#pragma unroll
            for (int t = K - 1; t > 0; --t) {
                if (dist[t] < dist[t - 1]) {
                    float td = dist[t]; dist[t] = dist[t - 1]; dist[t - 1] = td;
                    int ti = idx[t]; idx[t] = idx[t - 1]; idx[t - 1] = ti;
                }
            }
        }
    }
    int mywin = 0;
#pragma unroll
    for (int t = 0; t < K; t++) {
        float bd = dist[0]; int bi = idx[0];
#pragma unroll
        for (int off = 16; off > 0; off >>= 1) {
            float od = __shfl_down_sync(0xffffffffu, bd, off);
            int oi = __shfl_down_sync(0xffffffffu, bi, off);
            if (od < bd || (od == bd && oi < bi)) { bd = od; bi = oi; }
        }
        bi = __shfl_sync(0xffffffffu, bi, 0);
        if (lane == 0) outIdx[q * K + t] = bi;
        if (lane == t) mywin = bi;
        if (idx[0] == bi) {
#pragma unroll
            for (int tt = 0; tt < K - 1; tt++) { dist[tt] = dist[tt + 1]; idx[tt] = idx[tt + 1]; }
            dist[K - 1] = CUDART_INF_F; idx[K - 1] = 0x7fffffff;
        }
    }
    float e = 0.0f;
    if (WCALC) {
        if (lane < K) {
            float dx = qx - rx[mywin], dy = qy - ry[mywin], dz = qz - rz[mywin];
            float d = sqrtf(dx * dx + dy * dy + dz * dz + 1e-12f);
            e = expf(-d);
            wOut[q * K + lane] = e;
        }
#pragma unroll
        for (int off = 16; off > 0; off >>= 1)
            e += __shfl_down_sync(0xffffffffu, e, off);
    }
    return e;
}

// ---------------- feature tile (2-layer 1x1 conv), point-major out --------
template <int IN_CH, bool CLOUD>
__device__ void dev_feat(int n0, const float* __restrict__ src,
                         const float* __restrict__ W1, const float* __restrict__ b1,
                         const float* __restrict__ W2, const float* __restrict__ b2,
                         float* __restrict__ out, Smem& sm) {
    int tid = threadIdx.x;
    if (CLOUD) {
        for (int i = tid; i < IN_CH * 32; i += NTHR) {
            int c = i >> 5, p = i & 31;
            sm.feat.xin[i] = (n0 + p < N_PTS) ? src[(n0 + p) * 3 + c] : 0.0f;
        }
    } else {
        for (int i = tid; i < IN_CH * 32; i += NTHR) {
            int c = i >> 5, p = i & 31;
            sm.feat.xin[i] = (n0 + p < N_PTS) ? src[c * N_PTS + n0 + p] : 0.0f;
        }
    }
    for (int i = tid; i < 128 * 64 / 4; i += NTHR)
        ((float4*)sm.feat.W2s)[i] = ((const float4*)W2)[i];
    __syncthreads();

    int pt = tid & 31, g = tid >> 5;
#pragma unroll
    for (int cc = 0; cc < 8; cc++) {
        int ch = g * 8 + cc;
        float h = b1[ch];
#pragma unroll
        for (int i = 0; i < IN_CH; i++)
            h = fmaf(W1[ch * IN_CH + i], sm.feat.xin[i * 32 + pt], h);
        sm.feat.hid[ch * 32 + pt] = (h > 0.0f) ? h : 0.01f * h;
    }
    __syncthreads();

    int ch0 = g * 16;
    float acc[16];
#pragma unroll
    for (int i = 0; i < 16; i++) acc[i] = b2[ch0 + i];
#pragma unroll 4
    for (int j = 0; j < 64; j++) {
        float h = sm.feat.hid[j * 32 + pt];
#pragma unroll
        for (int i = 0; i < 16; i++)
            acc[i] = fmaf(sm.feat.W2s[(ch0 + i) * 64 + j], h, acc[i]);
    }
    int n = n0 + pt;
    if (n < N_PTS) {
#pragma unroll
        for (int i = 0; i < 16; i++) out[n * 128 + ch0 + i] = acc[i];
    }
    __syncthreads();
}

// ---------------- double-buffered 64x64 GEMM tile -------------------------
// XMODE: 0 plain X[k*xstride+col]; 1 xT X[col*xstride+k]; 2 lrelu(plain)
// OUTMODE: 2 store raw; 3 atomicAdd(RED) raw.
// WSUM: number of W partial buffers summed (1 or 4; stride WEFF_STR)
// PADX: X buffer padded -> unguarded float4 loads (XMODE 0/2 only)
template <int XMODE, int OUTMODE, int WSUM, int PADX>
__device__ void gemm_tile(const float* __restrict__ Wa,
                          int KW, int kLen,
                          const float* __restrict__ X, int xstride, int xn0, int Nx,
                          float* __restrict__ Y, int ystride,
                          int M, int Nout, int m0, int n0, Smem& sm) {
    int tid = threadIdx.x;
    int ty = tid >> 4, tx = tid & 15;
    float acc[4][4] = {};
    float4 pw, px4;
    float pxs[4];
    int wrow = (tid * 4) >> 4, wcol = (tid * 4) & 15;
    int xkr = tid >> 4, xc4 = (tid & 15) * 4;

    auto loadW = [&](int k0) {
        if (m0 + wrow < M) {
            int off = (m0 + wrow) * KW + k0 + wcol;
            pw = *(const float4*)&Wa[off];
            if (WSUM >= 4) {
                float4 w1 = *(const float4*)&Wa[off + WEFF_STR];
                float4 w2 = *(const float4*)&Wa[off + 2 * WEFF_STR];
                float4 w3 = *(const float4*)&Wa[off + 3 * WEFF_STR];
                pw.x += w1.x + w2.x + w3.x;
                pw.y += w1.y + w2.y + w3.y;
                pw.z += w1.z + w2.z + w3.z;
                pw.w += w1.w + w2.w + w3.w;
            }
        } else {
            pw = make_float4(0.f, 0.f, 0.f, 0.f);
        }
    };
    auto loadX = [&](int k0) {
        if (XMODE == 1) {
#pragma unroll
            for (int i = 0; i < 4; i++) {
                int l = tid + i * NTHR;
                int kr = l & 15, col = l >> 4;
                pxs[i] = (xn0 + col < Nx) ? X[(xn0 + col) * xstride + k0 + kr] : 0.0f;
            }
        } else if (PADX) {
            px4 = *(const float4*)&X[(k0 + xkr) * xstride + xn0 + xc4];
            if (XMODE == 2) {
                px4.x = (px4.x > 0.0f) ? px4.x : 0.01f * px4.x;
                px4.y = (px4.y > 0.0f) ? px4.y : 0.01f * px4.y;
                px4.z = (px4.z > 0.0f) ? px4.z : 0.01f * px4.z;
                px4.w = (px4.w > 0.0f) ? px4.w : 0.01f * px4.w;
            }
        } else {
            const float* row = &X[(k0 + xkr) * xstride + xn0];
            px4.x = (xn0 + xc4 + 0 < Nx) ? row[xc4 + 0] : 0.0f;
            px4.y = (xn0 + xc4 + 1 < Nx) ? row[xc4 + 1] : 0.0f;
            px4.z = (xn0 + xc4 + 2 < Nx) ? row[xc4 + 2] : 0.0f;
            px4.w = (xn0 + xc4 + 3 < Nx) ? row[xc4 + 3] : 0.0f;
            if (XMODE == 2) {
                px4.x = (px4.x > 0.0f) ? px4.x : 0.01f * px4.x;
                px4.y = (px4.y > 0.0f) ? px4.y : 0.01f * px4.y;
                px4.z = (px4.z > 0.0f) ? px4.z : 0.01f * px4.z;
                px4.w = (px4.w > 0.0f) ? px4.w : 0.01f * px4.w;
            }
        }
    };

    loadW(0); loadX(0);
    int p = 0;
    for (int k0 = 0; k0 < kLen; k0 += 16) {
        sm.gemm.Ws[p][wcol + 0][wrow] = pw.x;
        sm.gemm.Ws[p][wcol + 1][wrow] = pw.y;
        sm.gemm.Ws[p][wcol + 2][wrow] = pw.z;
        sm.gemm.Ws[p][wcol + 3][wrow] = pw.w;
        if (XMODE == 1) {
#pragma unroll
            for (int i = 0; i < 4; i++) {
                int l = tid + i * NTHR;
                sm.gemm.Xs[p][l & 15][l >> 4] = pxs[i];
            }
        } else {
            *(float4*)&sm.gemm.Xs[p][xkr][xc4] = px4;
        }
        __syncthreads();
        if (k0 + 16 < kLen) { loadW(k0 + 16); loadX(k0 + 16); }
#pragma unroll
        for (int kk = 0; kk < 16; kk++) {
            float4 a4 = *(const float4*)&sm.gemm.Ws[p][kk][ty * 4];
            float4 b4 = *(const float4*)&sm.gemm.Xs[p][kk][tx * 4];
            float a[4] = {a4.x, a4.y, a4.z, a4.w};
            float bb[4] = {b4.x, b4.y, b4.z, b4.w};
#pragma unroll
            for (int i = 0; i < 4; i++)
#pragma unroll
                for (int j = 0; j < 4; j++)
                    acc[i][j] = fmaf(a[i], bb[j], acc[i][j]);
        }
        p ^= 1;
    }
#pragma unroll
    for (int i = 0; i < 4; i++) {
        int m = m0 + ty * 4 + i;
        if (m >= M) continue;
#pragma unroll
        for (int j = 0; j < 4; j++) {
            int n = n0 + tx * 4 + j;
            if (n >= Nout) continue;
            if (OUTMODE == 3) atomicAdd(&Y[m * ystride + n], acc[i][j]);
            else              Y[m * ystride + n] = acc[i][j];
        }
    }
}

// --------------------------- megakernel -----------------------------------
__global__ void __launch_bounds__(NTHR, 4)
mega_kernel(const float* __restrict__ img, const float* __restrict__ cloud,
            const float* __restrict__ img_tar, const float* __restrict__ cloud_tar,
            const float* __restrict__ cur_feat, const float* __restrict__ tgt_feat,
            const float* __restrict__ Wc1, const float* __restrict__ bc1,
            const float* __restrict__ Wc2, const float* __restrict__ bc2,
            const float* __restrict__ Wp1, const float* __restrict__ bp1,
            const float* __restrict__ Wp2, const float* __restrict__ bp2,
            const float* __restrict__ Wfc1, const float* __restrict__ bfc1,
            const float* __restrict__ Wfc2, const float* __restrict__ bfc2,
            const float* __restrict__ Wfu2, const float* __restrict__ bfu2,
            const float* __restrict__ Wpn1, const float* __restrict__ bpn1,
            const float* __restrict__ Wpn2, const float* __restrict__ bpn2,
            const float* __restrict__ Wpn3, const float* __restrict__ bpn3,
            float* __restrict__ out) {
    __shared__ Smem sm;
    int b = blockIdx.x;
    int tid = threadIdx.x;

    // ---- P0: KNN (0-187) || feat (188-251) || Weff fold x4 (252-443)
    //          || V fold (444-467) || beff (468-471) || bF + cnt reset (472)
    if (b < KNN_BLKS) {
        SmemKNN& k = sm.knn;
        for (int i = tid; i < N_PTS; i += NTHR) {
            float x = cloud[i * 3 + 0], y = cloud[i * 3 + 1], z = cloud[i * 3 + 2];
            k.x0[i] = x; k.y0[i] = y; k.z0[i] = z; k.w0[i] = x * x + y * y + z * z;
            x = cloud_tar[i * 3 + 0]; y = cloud_tar[i * 3 + 1]; z = cloud_tar[i * 3 + 2];
            k.x1[i] = x; k.y1[i] = y; k.z1[i] = z; k.w1[i] = x * x + y * y + z * z;
        }
        if (tid < 16) k.wsum[tid >> 3][tid & 7] = 0.0f;
        __syncthreads();
        int w = tid >> 5;
        int qid = b * 8 + w;
        if (qid < 1500) {
            int task = (qid < 500) ? 0 : (qid < 1000 ? 1 : 2);
            int q = qid - task * 500;
            if (task == 0) {
                float s = knn_one<K12, true>(k.x0, k.y0, k.z0, k.w0,
                                             k.x1[q], k.y1[q], k.z1[q],
                                             g_inds, g_wct, q);
                if ((tid & 31) == 0) k.wsum[0][w] = s;
            } else if (task == 1) {
                float s = knn_one<K12, true>(k.x1, k.y1, k.z1, k.w1,
                                             k.x1[q], k.y1[q], k.z1[q],
                                             g_inds_self, g_wcc, q);
                if ((tid & 31) == 0) k.wsum[1][w] = s;
            } else {
                knn_one<KPP, false>(k.x1, k.y1, k.z1, k.w1,
                                    k.x0[q], k.y0[q], k.z0[q],
                                    g_inds_pp, nullptr, q);
            }
        }
        __syncthreads();
        if (tid == 0) {
            float s0 = 0.0f, s1 = 0.0f;
#pragma unroll
            for (int i = 0; i < 8; i++) { s0 += k.wsum[0][i]; s1 += k.wsum[1][i]; }
            g_ws0[b] = s0; g_ws1[b] = s1;
        }
    } else if (b < 252) {
        int u = b - KNN_BLKS;
        int task = u >> 4, n0 = (u & 15) * 32;
        if (task == 0)      dev_feat<3, true>(n0, cloud_tar, Wp1, bp1, Wp2, bp2, g_cfT, sm);
        else if (task == 1) dev_feat<3, true>(n0, cloud, Wp1, bp1, Wp2, bp2, g_ctfT, sm);
        else if (task == 2) dev_feat<32, false>(n0, img_tar, Wc1, bc1, Wc2, bc2, g_icT, sm);
        else                dev_feat<32, false>(n0, img, Wc1, bc1, Wc2, bc2, g_itT, sm);
    } else if (b < 444) {
        int u = b - 252;  // 192 blocks: split-K x4 of Wpn2@Wpn1, 48 tiles each
        int quarter = u & 3, t = u >> 2;  // t: 0..47 = 16m x 3n
        gemm_tile<0, 2, 1, 0>(Wpn2 + quarter * 64, 256, 64,
                              Wpn1 + quarter * 64 * 160, 160, (t % 3) * 64, 160,
                              g_Weffp + quarter * WEFF_STR, 160, 1024, 160,
                              (t / 3) * 64, (t % 3) * 64, sm);
    } else if (b < 468) {
        int u = b - 444;  // V fold: 2 halves x 3m x 4n, K=64 (exact-fit X)
        int v1 = (u >= 12) ? 1 : 0; int t = u - v1 * 12;
        gemm_tile<0, 2, 1, 1>(Wfu2 + v1 * 64, 128, 64,
                              v1 ? Wfc1 : Wfc2, 256, (t % 4) * 64, 256,
                              g_V, 512, 160, 512,
                              (t / 4) * 64, (t % 4) * 64 + v1 * 256, sm);
    } else if (b < 472) {
        int base = (b - 468) * 256;
        for (int m = base + tid; m < base + 256; m += NTHR) {
            float a0 = 0.0f, a1 = 0.0f, a2 = 0.0f, a3 = 0.0f;
            const float* wr = Wpn2 + m * 256;
            for (int kk = 0; kk < 256; kk += 4) {
                a0 = fmaf(wr[kk], bpn1[kk], a0);
                a1 = fmaf(wr[kk + 1], bpn1[kk + 1], a1);
                a2 = fmaf(wr[kk + 2], bpn1[kk + 2], a2);
                a3 = fmaf(wr[kk + 3], bpn1[kk + 3], a3);
            }
            g_beff[m] = bpn2[m] + ((a0 + a1) + (a2 + a3));
        }
    } else if (b == 472) {
        if (tid < 160) {
            float a0 = 0.0f, a1 = 0.0f;
            const float* wr = Wfu2 + tid * 128;
            for (int kk = 0; kk < 64; kk++) {
                a0 = fmaf(wr[kk], bfc2[kk], a0);
                a1 = fmaf(wr[64 + kk], bfc1[kk], a1);
            }
            g_bF[tid] = bfu2[tid] + a0 + a1;
        }
        if (tid < 8) g_cnt[tid] = 0u;  // replay-safe reset (ordered by bars 0..3)
    }
    gridbar(0);

    // ---- P1: pool1 (blocks 0-499) || init F = bF over stride-512 (500-511)
    if (b < 500) {
        float inv = block_inv(g_ws0, sm);
        int half = tid >> 7, ch = tid & 127;
        int n = b;
        if (half == 0) {
            float mi = -CUDART_INF_F;
#pragma unroll
            for (int kk = 0; kk < K12; kk++) {
                int i = g_inds[n * K12 + kk];
                mi = fmaxf(mi, g_itT[i * 128 + ch] * (g_wct[n * K12 + kk] * inv));
            }
            g_cat[n * 512 + 256 + ch] = g_icT[n * 128 + ch] - mi;  // img_diff
        } else {
            float mp = -CUDART_INF_F;
#pragma unroll
            for (int kk = 0; kk < K12; kk++) {
                int i = g_inds[n * K12 + kk];
                mp = fmaxf(mp, g_ctfT[i * 128 + ch] * (g_wct[n * K12 + kk] * inv));
            }
            g_cat[n * 512 + ch] = g_cfT[n * 128 + ch] - mp;  // cloud_diff
        }
    } else {
        for (int e = (b - 500) * NTHR + tid; e < 160 * NSTR; e += 12 * NTHR)
            g_F[e] = g_bF[e >> 9];
    }
    gridbar(1);

    // ---- P2: pool2 (blocks 0-249, 2 pts each) || P3a: F += V@catT over
    //          K-ranges [0,128)+[256,384) (blocks 250-441)
    if (b < 250) {
        float inv = block_inv(g_ws1, sm);
        int sub = tid >> 7, ch = tid & 127;
        int n = b * 2 + sub;
        float mspd = -CUDART_INF_F, msid = -CUDART_INF_F;
#pragma unroll
        for (int kk = 0; kk < K12; kk++) {
            int i = g_inds_self[n * K12 + kk];
            float w = g_wcc[n * K12 + kk] * inv;
            mspd = fmaxf(mspd, g_cat[i * 512 + ch] * w);        // cloud_diff
            msid = fmaxf(msid, g_cat[i * 512 + 256 + ch] * w);  // img_diff
        }
        g_cat[n * 512 + 384 + ch] = mspd;  // spd
        g_cat[n * 512 + 128 + ch] = msid;  // sid
    } else if (b < 442) {
        int u = b - 250;
        int r = u & 1, slab = (u >> 1) & 3, t = u >> 3;  // t: 0..23 = 3m x 8n
        int kb = r * 256 + slab * 32;
        gemm_tile<1, 3, 1, 0>(g_V + kb, 512, 32,
                              g_cat + kb, 512, (t & 7) * 64, 512,
                              g_F, NSTR, 160, 512, (t >> 3) * 64, (t & 7) * 64, sm);
    }
    gridbar(2);

    // ---- P3b: F += V@catT over K-ranges [128,256)+[384,512) (blocks 0-191)
    //           || init X2 = beff, X3 = bpn3 (blocks 192-511)
    if (b < 192) {
        int r = b & 1, slab = (b >> 1) & 3, t = b >> 3;  // t: 0..23 = 3m x 8n
        int kb = 128 + r * 256 + slab * 32;
        gemm_tile<1, 3, 1, 0>(g_V + kb, 512, 32,
                              g_cat + kb, 512, (t & 7) * 64, 512,
                              g_F, NSTR, 160, 512, (t >> 3) * 64, (t & 7) * 64, sm);
    } else {
        int u = b - 192;  // 320 blocks
        for (int e = u * NTHR + tid; e < 1024 * NSTR; e += 320 * NTHR)
            g_X2[e] = g_beff[e >> 9];
        for (int e = u * NTHR + tid; e < 160 * NSTR; e += 320 * NTHR)
            g_X3[e] = bpn3[e >> 9];
    }
    gridbar(3);

    // ---- P4: X2 += (sum of 4 Weff partials) @ F  (split-K x2, blocks 0-255),
    //          each tile signals its 128-row X2 block counter on completion.
    if (b < 256) {
        int half = b & 1, t = b >> 1;  // t: 0..127 = 16m x 8n
        gemm_tile<0, 3, 4, 1>(g_Weffp + half * 80, 160, 80,
                              g_F + half * 80 * NSTR, NSTR, (t & 7) * 64, 512,
                              g_X2, NSTR, 1024, 512, (t >> 3) * 64, (t & 7) * 64, sm);
        __threadfence();
        __syncthreads();
        if (tid == 0) atomicAdd(&g_cnt[t >> 4], 1u);  // rowblock = m0/128
    }
    // (no grid barrier: P5 consumes via per-rowblock counters)

    // ---- P5: X3 += Wpn3 @ lrelu(X2)  (split-K x8, blocks 0-191), gated on
    //          its X2 rowblock being complete (32 tile-completions).
    if (b < 192) {
        int slab = b & 7, t = b >> 3;  // t: 0..23 = 3m x 8n
        if (tid == 0) {
            while (*(volatile unsigned*)&g_cnt[slab] < 32u) {}
            __threadfence();
        }
        __syncthreads();
        gemm_tile<2, 3, 1, 1>(Wpn3 + slab * 128, 1024, 128,
                              g_X2 + slab * 128 * NSTR, NSTR, (t & 7) * 64, 512,
                              g_X3, NSTR, 160, 512, (t >> 3) * 64, (t & 7) * 64, sm);
    }
    gridbar(5);

    // ---- P6: final gather-mean (blocks 0-499)
    if (b < 500 && tid < 160) {
        int n = b;
        float s = 0.0f;
#pragma unroll
        for (int kk = 0; kk < KPP; kk++) {
            int i = g_inds_pp[n * KPP + kk];
            s += tgt_feat[tid * N_PTS + i] * g_X3[tid * NSTR + i];
        }
        out[tid * N_PTS + n] = cur_feat[tid * N_PTS + n] + 0.25f * s;
    }
}

// --------------------------------------------------------------------------
extern "C" void kernel_launch(void* const* d_in, const int* in_sizes, int n_in,
                              void* d_out, int out_size) {
    mega_kernel<<<NBLK, NTHR>>>(
        (const float*)d_in[0],  (const float*)d_in[1],
        (const float*)d_in[2],  (const float*)d_in[3],
        (const float*)d_in[4],  (const float*)d_in[5],
        (const float*)d_in[6],  (const float*)d_in[7],
        (const float*)d_in[8],  (const float*)d_in[9],
        (const float*)d_in[10], (const float*)d_in[11],
        (const float*)d_in[12], (const float*)d_in[13],
        (const float*)d_in[14], (const float*)d_in[15],
        (const float*)d_in[16], (const float*)d_in[17],
        (const float*)d_in[18], (const float*)d_in[19],
        (const float*)d_in[20], (const float*)d_in[21],
        (const float*)d_in[22], (const float*)d_in[23],
        (const float*)d_in[24], (const float*)d_in[25],
        (float*)d_out);
}

// round 17
// speedup vs baseline: 1.1783x; 1.0431x over previous
#include <cuda_runtime.h>
#include <math_constants.h>

#define N_PTS 500
#define NSTR 512
#define K12 12
#define KPP 4
#define NBLK 512
#define NTHR 256
#define KNN_BLKS 188
#define WEFF_STR (1024 * 160)

// ---------------- scratch (device globals; no allocation) ----------------
__device__ float g_cfT[N_PTS * 128];
__device__ float g_ctfT[N_PTS * 128];
__device__ float g_icT[N_PTS * 128];
__device__ float g_itT[N_PTS * 128];
__device__ int   g_inds[N_PTS * K12];
__device__ int   g_inds_self[N_PTS * K12];
__device__ int   g_inds_pp[N_PTS * KPP];
__device__ float g_wct[N_PTS * K12];
__device__ float g_wcc[N_PTS * K12];
__device__ float g_ws0[192];
__device__ float g_ws1[192];
__device__ float g_cat[NSTR * 512];       // padded rows 500-511 stay 0 (zero-init)
__device__ float g_V[160 * 512];          // folded fuse2@fc weights
__device__ float g_bF[160];
__device__ float g_Weffp[4 * WEFF_STR];   // split-K x4 partials of Wpn2@Wpn1
__device__ float g_beff[1024];
__device__ float g_F[160 * NSTR];         // init bF, RED-accumulated (stride 512)
__device__ float g_X2[1024 * NSTR];       // init beff, RED-accumulated
__device__ float g_X3[160 * NSTR];        // init bpn3, RED-accumulated

// ---------------- sync state (monotonic barrier + dataflow counters) ------
__device__ unsigned g_count[8];           // barrier slots (monotonic, no reset)
__device__ unsigned g_p2cnt[8];           // pool2 point-group completions
__device__ unsigned g_x2cnt[8];           // P4 X2 rowblock completions
__device__ unsigned g_fcnt;               // F tile completions (384)
__device__ unsigned g_icnt;               // X2/X3 init completions (70)
__device__ unsigned g_x3cnt;              // P5 tile completions (192)

__device__ __forceinline__ void gridbar(int slot) {
    __syncthreads();
    if (threadIdx.x == 0) {
        __threadfence();
        unsigned old = atomicAdd(&g_count[slot], 1u) + 1u;
        unsigned target = ((old + NBLK - 1u) / NBLK) * NBLK;
        while (*(volatile unsigned*)&g_count[slot] < target) {}
        __threadfence();
    }
    __syncthreads();
}

// producers: all threads fence, then one signal
#define SIGNAL(cnt)                                         \
    do {                                                    \
        __threadfence();                                    \
        __syncthreads();                                    \
        if (threadIdx.x == 0) atomicAdd(&(cnt), 1u);        \
    } while (0)

// ---------------- shared memory union -------------------------------------
struct SmemKNN {
    float x0[N_PTS], y0[N_PTS], z0[N_PTS], w0[N_PTS];
    float x1[N_PTS], y1[N_PTS], z1[N_PTS], w1[N_PTS];
    float wsum[2][8];
};
struct SmemFeat { float W2s[128 * 64]; float xin[32 * 32]; float hid[64 * 32]; };
struct SmemGemm { float Ws[2][16][68]; float Xs[2][16][68]; };
struct SmemPool { float red[8]; float inv; };
union __align__(16) Smem {
    SmemKNN knn;
    SmemFeat feat;
    SmemGemm gemm;
    SmemPool pool;
};

// deterministic per-block softmax-denominator reduction (identical all blocks)
__device__ float block_inv(const float* __restrict__ arr, Smem& sm) {
    int tid = threadIdx.x;
    float v = (tid < KNN_BLKS) ? arr[tid] : 0.0f;
#pragma unroll
    for (int off = 16; off > 0; off >>= 1)
        v += __shfl_down_sync(0xffffffffu, v, off);
    if ((tid & 31) == 0) sm.pool.red[tid >> 5] = v;
    __syncthreads();
    if (tid == 0) {
        float s = 0.0f;
#pragma unroll
        for (int i = 0; i < 8; i++) s += sm.pool.red[i];
        sm.pool.inv = 1.0f / s;
    }
    __syncthreads();
    return sm.pool.inv;
}

// ---------------- warp-cooperative KNN ------------------------------------
template <int K, bool WCALC>
__device__ float knn_one(const float* __restrict__ rx, const float* __restrict__ ry,
                         const float* __restrict__ rz, const float* __restrict__ rr,
                         float qx, float qy, float qz,
                         int* __restrict__ outIdx, float* __restrict__ wOut, int q) {
    int lane = threadIdx.x & 31;
    float qq = qx * qx + qy * qy + qz * qz;
    float dist[K]; int idx[K];
#pragma unroll
    for (int t = 0; t < K; t++) { dist[t] = CUDART_INF_F; idx[t] = 0x7fffffff; }
    for (int r = lane; r < N_PTS; r += 32) {
        float d2 = qq - 2.0f * (qx * rx[r] + qy * ry[r] + qz * rz[r]) + rr[r];
        if (d2 < dist[K - 1]) {
            dist[K - 1] = d2; idx[K - 1] = r;
#pragma unroll
            for (int t = K - 1; t > 0; --t) {
                if (dist[t] < dist[t - 1]) {
                    float td = dist[t]; dist[t] = dist[t - 1]; dist[t - 1] = td;
                    int ti = idx[t]; idx[t] = idx[t - 1]; idx[t - 1] = ti;
                }
            }
        }
    }
    int mywin = 0;
#pragma unroll
    for (int t = 0; t < K; t++) {
        float bd = dist[0]; int bi = idx[0];
#pragma unroll
        for (int off = 16; off > 0; off >>= 1) {
            float od = __shfl_down_sync(0xffffffffu, bd, off);
            int oi = __shfl_down_sync(0xffffffffu, bi, off);
            if (od < bd || (od == bd && oi < bi)) { bd = od; bi = oi; }
        }
        bi = __shfl_sync(0xffffffffu, bi, 0);
        if (lane == 0) outIdx[q * K + t] = bi;
        if (lane == t) mywin = bi;
        if (idx[0] == bi) {
#pragma unroll
            for (int tt = 0; tt < K - 1; tt++) { dist[tt] = dist[tt + 1]; idx[tt] = idx[tt + 1]; }
            dist[K - 1] = CUDART_INF_F; idx[K - 1] = 0x7fffffff;
        }
    }
    float e = 0.0f;
    if (WCALC) {
        if (lane < K) {
            float dx = qx - rx[mywin], dy = qy - ry[mywin], dz = qz - rz[mywin];
            float d = sqrtf(dx * dx + dy * dy + dz * dz + 1e-12f);
            e = expf(-d);
            wOut[q * K + lane] = e;
        }
#pragma unroll
        for (int off = 16; off > 0; off >>= 1)
            e += __shfl_down_sync(0xffffffffu, e, off);
    }
    return e;
}

// ---------------- feature tile (2-layer 1x1 conv), point-major out --------
template <int IN_CH, bool CLOUD>
__device__ void dev_feat(int n0, const float* __restrict__ src,
                         const float* __restrict__ W1, const float* __restrict__ b1,
                         const float* __restrict__ W2, const float* __restrict__ b2,
                         float* __restrict__ out, Smem& sm) {
    int tid = threadIdx.x;
    if (CLOUD) {
        for (int i = tid; i < IN_CH * 32; i += NTHR) {
            int c = i >> 5, p = i & 31;
            sm.feat.xin[i] = (n0 + p < N_PTS) ? src[(n0 + p) * 3 + c] : 0.0f;
        }
    } else {
        for (int i = tid; i < IN_CH * 32; i += NTHR) {
            int c = i >> 5, p = i & 31;
            sm.feat.xin[i] = (n0 + p < N_PTS) ? src[c * N_PTS + n0 + p] : 0.0f;
        }
    }
    for (int i = tid; i < 128 * 64 / 4; i += NTHR)
        ((float4*)sm.feat.W2s)[i] = ((const float4*)W2)[i];
    __syncthreads();

    int pt = tid & 31, g = tid >> 5;
#pragma unroll
    for (int cc = 0; cc < 8; cc++) {
        int ch = g * 8 + cc;
        float h = b1[ch];
#pragma unroll
        for (int i = 0; i < IN_CH; i++)
            h = fmaf(W1[ch * IN_CH + i], sm.feat.xin[i * 32 + pt], h);
        sm.feat.hid[ch * 32 + pt] = (h > 0.0f) ? h : 0.01f * h;
    }
    __syncthreads();

    int ch0 = g * 16;
    float acc[16];
#pragma unroll
    for (int i = 0; i < 16; i++) acc[i] = b2[ch0 + i];
#pragma unroll 4
    for (int j = 0; j < 64; j++) {
        float h = sm.feat.hid[j * 32 + pt];
#pragma unroll
        for (int i = 0; i < 16; i++)
            acc[i] = fmaf(sm.feat.W2s[(ch0 + i) * 64 + j], h, acc[i]);
    }
    int n = n0 + pt;
    if (n < N_PTS) {
#pragma unroll
        for (int i = 0; i < 16; i++) out[n * 128 + ch0 + i] = acc[i];
    }
    __syncthreads();
}

// ---------------- double-buffered 64x64 GEMM tile -------------------------
// XMODE: 0 plain X[k*xstride+col]; 1 xT X[col*xstride+k]; 2 lrelu(plain)
// OUTMODE: 2 store raw; 3 atomicAdd(RED) raw.
// WSUM: number of W partial buffers summed (1 or 4; stride WEFF_STR)
// PADX: X buffer padded -> unguarded float4 loads (XMODE 0/2 only)
template <int XMODE, int OUTMODE, int WSUM, int PADX>
__device__ void gemm_tile(const float* __restrict__ Wa,
                          int KW, int kLen,
                          const float* __restrict__ X, int xstride, int xn0, int Nx,
                          float* __restrict__ Y, int ystride,
                          int M, int Nout, int m0, int n0, Smem& sm) {
    int tid = threadIdx.x;
    int ty = tid >> 4, tx = tid & 15;
    float acc[4][4] = {};
    float4 pw, px4;
    float pxs[4];
    int wrow = (tid * 4) >> 4, wcol = (tid * 4) & 15;
    int xkr = tid >> 4, xc4 = (tid & 15) * 4;

    auto loadW = [&](int k0) {
        if (m0 + wrow < M) {
            int off = (m0 + wrow) * KW + k0 + wcol;
            pw = *(const float4*)&Wa[off];
            if (WSUM >= 4) {
                float4 w1 = *(const float4*)&Wa[off + WEFF_STR];
                float4 w2 = *(const float4*)&Wa[off + 2 * WEFF_STR];
                float4 w3 = *(const float4*)&Wa[off + 3 * WEFF_STR];
                pw.x += w1.x + w2.x + w3.x;
                pw.y += w1.y + w2.y + w3.y;
                pw.z += w1.z + w2.z + w3.z;
                pw.w += w1.w + w2.w + w3.w;
            }
        } else {
            pw = make_float4(0.f, 0.f, 0.f, 0.f);
        }
    };
    auto loadX = [&](int k0) {
        if (XMODE == 1) {
#pragma unroll
            for (int i = 0; i < 4; i++) {
                int l = tid + i * NTHR;
                int kr = l & 15, col = l >> 4;
                pxs[i] = (xn0 + col < Nx) ? X[(xn0 + col) * xstride + k0 + kr] : 0.0f;
            }
        } else if (PADX) {
            px4 = *(const float4*)&X[(k0 + xkr) * xstride + xn0 + xc4];
            if (XMODE == 2) {
                px4.x = (px4.x > 0.0f) ? px4.x : 0.01f * px4.x;
                px4.y = (px4.y > 0.0f) ? px4.y : 0.01f * px4.y;
                px4.z = (px4.z > 0.0f) ? px4.z : 0.01f * px4.z;
                px4.w = (px4.w > 0.0f) ? px4.w : 0.01f * px4.w;
            }
        } else {
            const float* row = &X[(k0 + xkr) * xstride + xn0];
            px4.x = (xn0 + xc4 + 0 < Nx) ? row[xc4 + 0] : 0.0f;
            px4.y = (xn0 + xc4 + 1 < Nx) ? row[xc4 + 1] : 0.0f;
            px4.z = (xn0 + xc4 + 2 < Nx) ? row[xc4 + 2] : 0.0f;
            px4.w = (xn0 + xc4 + 3 < Nx) ? row[xc4 + 3] : 0.0f;
            if (XMODE == 2) {
                px4.x = (px4.x > 0.0f) ? px4.x : 0.01f * px4.x;
                px4.y = (px4.y > 0.0f) ? px4.y : 0.01f * px4.y;
                px4.z = (px4.z > 0.0f) ? px4.z : 0.01f * px4.z;
                px4.w = (px4.w > 0.0f) ? px4.w : 0.01f * px4.w;
            }
        }
    };

    loadW(0); loadX(0);
    int p = 0;
    for (int k0 = 0; k0 < kLen; k0 += 16) {
        sm.gemm.Ws[p][wcol + 0][wrow] = pw.x;
        sm.gemm.Ws[p][wcol + 1][wrow] = pw.y;
        sm.gemm.Ws[p][wcol + 2][wrow] = pw.z;
        sm.gemm.Ws[p][wcol + 3][wrow] = pw.w;
        if (XMODE == 1) {
#pragma unroll
            for (int i = 0; i < 4; i++) {
                int l = tid + i * NTHR;
                sm.gemm.Xs[p][l & 15][l >> 4] = pxs[i];
            }
        } else {
            *(float4*)&sm.gemm.Xs[p][xkr][xc4] = px4;
        }
        __syncthreads();
        if (k0 + 16 < kLen) { loadW(k0 + 16); loadX(k0 + 16); }
#pragma unroll
        for (int kk = 0; kk < 16; kk++) {
            float4 a4 = *(const float4*)&sm.gemm.Ws[p][kk][ty * 4];
            float4 b4 = *(const float4*)&sm.gemm.Xs[p][kk][tx * 4];
            float a[4] = {a4.x, a4.y, a4.z, a4.w};
            float bb[4] = {b4.x, b4.y, b4.z, b4.w};
#pragma unroll
            for (int i = 0; i < 4; i++)
#pragma unroll
                for (int j = 0; j < 4; j++)
                    acc[i][j] = fmaf(a[i], bb[j], acc[i][j]);
        }
        p ^= 1;
    }
#pragma unroll
    for (int i = 0; i < 4; i++) {
        int m = m0 + ty * 4 + i;
        if (m >= M) continue;
#pragma unroll
        for (int j = 0; j < 4; j++) {
            int n = n0 + tx * 4 + j;
            if (n >= Nout) continue;
            if (OUTMODE == 3) atomicAdd(&Y[m * ystride + n], acc[i][j]);
            else              Y[m * ystride + n] = acc[i][j];
        }
    }
}

// --------------------------- megakernel -----------------------------------
__global__ void __launch_bounds__(NTHR, 4)
mega_kernel(const float* __restrict__ img, const float* __restrict__ cloud,
            const float* __restrict__ img_tar, const float* __restrict__ cloud_tar,
            const float* __restrict__ cur_feat, const float* __restrict__ tgt_feat,
            const float* __restrict__ Wc1, const float* __restrict__ bc1,
            const float* __restrict__ Wc2, const float* __restrict__ bc2,
            const float* __restrict__ Wp1, const float* __restrict__ bp1,
            const float* __restrict__ Wp2, const float* __restrict__ bp2,
            const float* __restrict__ Wfc1, const float* __restrict__ bfc1,
            const float* __restrict__ Wfc2, const float* __restrict__ bfc2,
            const float* __restrict__ Wfu2, const float* __restrict__ bfu2,
            const float* __restrict__ Wpn1, const float* __restrict__ bpn1,
            const float* __restrict__ Wpn2, const float* __restrict__ bpn2,
            const float* __restrict__ Wpn3, const float* __restrict__ bpn3,
            float* __restrict__ out) {
    __shared__ Smem sm;
    int b = blockIdx.x;
    int tid = threadIdx.x;

    // ---- P0: KNN (0-187) || feat (188-251) || Weff fold x4 (252-443)
    //          || V fold (444-467) || beff (468-471) || bF + counter reset (472)
    if (b < KNN_BLKS) {
        SmemKNN& k = sm.knn;
        for (int i = tid; i < N_PTS; i += NTHR) {
            float x = cloud[i * 3 + 0], y = cloud[i * 3 + 1], z = cloud[i * 3 + 2];
            k.x0[i] = x; k.y0[i] = y; k.z0[i] = z; k.w0[i] = x * x + y * y + z * z;
            x = cloud_tar[i * 3 + 0]; y = cloud_tar[i * 3 + 1]; z = cloud_tar[i * 3 + 2];
            k.x1[i] = x; k.y1[i] = y; k.z1[i] = z; k.w1[i] = x * x + y * y + z * z;
        }
        if (tid < 16) k.wsum[tid >> 3][tid & 7] = 0.0f;
        __syncthreads();
        int w = tid >> 5;
        int qid = b * 8 + w;
        if (qid < 1500) {
            int task = (qid < 500) ? 0 : (qid < 1000 ? 1 : 2);
            int q = qid - task * 500;
            if (task == 0) {
                float s = knn_one<K12, true>(k.x0, k.y0, k.z0, k.w0,
                                             k.x1[q], k.y1[q], k.z1[q],
                                             g_inds, g_wct, q);
                if ((tid & 31) == 0) k.wsum[0][w] = s;
            } else if (task == 1) {
                float s = knn_one<K12, true>(k.x1, k.y1, k.z1, k.w1,
                                             k.x1[q], k.y1[q], k.z1[q],
                                             g_inds_self, g_wcc, q);
                if ((tid & 31) == 0) k.wsum[1][w] = s;
            } else {
                knn_one<KPP, false>(k.x1, k.y1, k.z1, k.w1,
                                    k.x0[q], k.y0[q], k.z0[q],
                                    g_inds_pp, nullptr, q);
            }
        }
        __syncthreads();
        if (tid == 0) {
            float s0 = 0.0f, s1 = 0.0f;
#pragma unroll
            for (int i = 0; i < 8; i++) { s0 += k.wsum[0][i]; s1 += k.wsum[1][i]; }
            g_ws0[b] = s0; g_ws1[b] = s1;
        }
    } else if (b < 252) {
        int u = b - KNN_BLKS;
        int task = u >> 4, n0 = (u & 15) * 32;
        if (task == 0)      dev_feat<3, true>(n0, cloud_tar, Wp1, bp1, Wp2, bp2, g_cfT, sm);
        else if (task == 1) dev_feat<3, true>(n0, cloud, Wp1, bp1, Wp2, bp2, g_ctfT, sm);
        else if (task == 2) dev_feat<32, false>(n0, img_tar, Wc1, bc1, Wc2, bc2, g_icT, sm);
        else                dev_feat<32, false>(n0, img, Wc1, bc1, Wc2, bc2, g_itT, sm);
    } else if (b < 444) {
        int u = b - 252;  // 192 blocks: split-K x4 of Wpn2@Wpn1, 48 tiles each
        int quarter = u & 3, t = u >> 2;  // t: 0..47 = 16m x 3n
        gemm_tile<0, 2, 1, 0>(Wpn2 + quarter * 64, 256, 64,
                              Wpn1 + quarter * 64 * 160, 160, (t % 3) * 64, 160,
                              g_Weffp + quarter * WEFF_STR, 160, 1024, 160,
                              (t / 3) * 64, (t % 3) * 64, sm);
    } else if (b < 468) {
        int u = b - 444;  // V fold: 2 halves x 3m x 4n, K=64 (exact-fit X)
        int v1 = (u >= 12) ? 1 : 0; int t = u - v1 * 12;
        gemm_tile<0, 2, 1, 1>(Wfu2 + v1 * 64, 128, 64,
                              v1 ? Wfc1 : Wfc2, 256, (t % 4) * 64, 256,
                              g_V, 512, 160, 512,
                              (t / 4) * 64, (t % 4) * 64 + v1 * 256, sm);
    } else if (b < 472) {
        int base = (b - 468) * 256;
        for (int m = base + tid; m < base + 256; m += NTHR) {
            float a0 = 0.0f, a1 = 0.0f, a2 = 0.0f, a3 = 0.0f;
            const float* wr = Wpn2 + m * 256;
            for (int kk = 0; kk < 256; kk += 4) {
                a0 = fmaf(wr[kk], bpn1[kk], a0);
                a1 = fmaf(wr[kk + 1], bpn1[kk + 1], a1);
                a2 = fmaf(wr[kk + 2], bpn1[kk + 2], a2);
                a3 = fmaf(wr[kk + 3], bpn1[kk + 3], a3);
            }
            g_beff[m] = bpn2[m] + ((a0 + a1) + (a2 + a3));
        }
    } else if (b == 472) {
        if (tid < 160) {
            float a0 = 0.0f, a1 = 0.0f;
            const float* wr = Wfu2 + tid * 128;
            for (int kk = 0; kk < 64; kk++) {
                a0 = fmaf(wr[kk], bfc2[kk], a0);
                a1 = fmaf(wr[64 + kk], bfc1[kk], a1);
            }
            g_bF[tid] = bfu2[tid] + a0 + a1;
        }
        if (tid < 8) { g_p2cnt[tid] = 0u; g_x2cnt[tid] = 0u; }
        if (tid == 8) { g_fcnt = 0u; g_icnt = 0u; g_x3cnt = 0u; }
    }
    gridbar(0);

    // ---- P1: pool1 (blocks 0-499) || init F = bF over stride-512 (500-511)
    if (b < 500) {
        float inv = block_inv(g_ws0, sm);
        int half = tid >> 7, ch = tid & 127;
        int n = b;
        if (half == 0) {
            float mi = -CUDART_INF_F;
#pragma unroll
            for (int kk = 0; kk < K12; kk++) {
                int i = g_inds[n * K12 + kk];
                mi = fmaxf(mi, g_itT[i * 128 + ch] * (g_wct[n * K12 + kk] * inv));
            }
            g_cat[n * 512 + 256 + ch] = g_icT[n * 128 + ch] - mi;  // img_diff
        } else {
            float mp = -CUDART_INF_F;
#pragma unroll
            for (int kk = 0; kk < K12; kk++) {
                int i = g_inds[n * K12 + kk];
                mp = fmaxf(mp, g_ctfT[i * 128 + ch] * (g_wct[n * K12 + kk] * inv));
            }
            g_cat[n * 512 + ch] = g_cfT[n * 128 + ch] - mp;  // cloud_diff
        }
    } else {
        for (int e = (b - 500) * NTHR + tid; e < 160 * NSTR; e += 12 * NTHR)
            g_F[e] = g_bF[e >> 9];
    }
    gridbar(1);

    // ---- P2 region: pool2 (0-249, signal groups) || P3a (250-441, signal F)
    //                 || X2/X3 init (442-511, signal icnt)
    if (b < 250) {
        float inv = block_inv(g_ws1, sm);
        int sub = tid >> 7, ch = tid & 127;
        int n = b * 2 + sub;
        float mspd = -CUDART_INF_F, msid = -CUDART_INF_F;
#pragma unroll
        for (int kk = 0; kk < K12; kk++) {
            int i = g_inds_self[n * K12 + kk];
            float w = g_wcc[n * K12 + kk] * inv;
            mspd = fmaxf(mspd, g_cat[i * 512 + ch] * w);        // cloud_diff
            msid = fmaxf(msid, g_cat[i * 512 + 256 + ch] * w);  // img_diff
        }
        g_cat[n * 512 + 384 + ch] = mspd;  // spd
        g_cat[n * 512 + 128 + ch] = msid;  // sid
        SIGNAL(g_p2cnt[b >> 5]);
    } else if (b < 442) {
        int u = b - 250;
        int r = u & 1, slab = (u >> 1) & 3, t = u >> 3;  // t: 0..23 = 3m x 8n
        int kb = r * 256 + slab * 32;
        gemm_tile<1, 3, 1, 0>(g_V + kb, 512, 32,
                              g_cat + kb, 512, (t & 7) * 64, 512,
                              g_F, NSTR, 160, 512, (t >> 3) * 64, (t & 7) * 64, sm);
        SIGNAL(g_fcnt);
    } else {
        int u = b - 442;  // 70 blocks
        for (int e = u * NTHR + tid; e < 1024 * NSTR; e += 70 * NTHR)
            g_X2[e] = g_beff[e >> 9];
        for (int e = u * NTHR + tid; e < 160 * NSTR; e += 70 * NTHR)
            g_X3[e] = bpn3[e >> 9];
        SIGNAL(g_icnt);
    }

    // ---- P3b: F += V@catT over sid/spd K-ranges, gated on pool2 point-groups
    if (b < 192) {
        int r = b & 1, slab = (b >> 1) & 3, t = b >> 3;  // t: 0..23 = 3m x 8n
        int grp = t & 7;
        unsigned tgt = (grp == 7) ? 26u : 32u;
        if (tid == 0) {
            while (*(volatile unsigned*)&g_p2cnt[grp] < tgt) {}
            __threadfence();
        }
        __syncthreads();
        int kb = 128 + r * 256 + slab * 32;
        gemm_tile<1, 3, 1, 0>(g_V + kb, 512, 32,
                              g_cat + kb, 512, (t & 7) * 64, 512,
                              g_F, NSTR, 160, 512, (t >> 3) * 64, (t & 7) * 64, sm);
        SIGNAL(g_fcnt);
    }

    // ---- P4: X2 += Weff @ F  (split-K x2, blocks 0-255), gated on F + init
    if (b < 256) {
        if (tid == 0) {
            while (*(volatile unsigned*)&g_fcnt < 384u ||
                   *(volatile unsigned*)&g_icnt < 70u) {}
            __threadfence();
        }
        __syncthreads();
        int half = b & 1, t = b >> 1;  // t: 0..127 = 16m x 8n
        gemm_tile<0, 3, 4, 1>(g_Weffp + half * 80, 160, 80,
                              g_F + half * 80 * NSTR, NSTR, (t & 7) * 64, 512,
                              g_X2, NSTR, 1024, 512, (t >> 3) * 64, (t & 7) * 64, sm);
        SIGNAL(g_x2cnt[t >> 4]);  // rowblock = m0/128
    }

    // ---- P5: X3 += Wpn3 @ lrelu(X2)  (split-K x8, blocks 0-191),
    //          gated on X2 rowblock (32 tile-completions)
    if (b < 192) {
        int slab = b & 7, t = b >> 3;  // t: 0..23 = 3m x 8n
        if (tid == 0) {
            while (*(volatile unsigned*)&g_x2cnt[slab] < 32u) {}
            __threadfence();
        }
        __syncthreads();
        gemm_tile<2, 3, 1, 1>(Wpn3 + slab * 128, 1024, 128,
                              g_X2 + slab * 128 * NSTR, NSTR, (t & 7) * 64, 512,
                              g_X3, NSTR, 160, 512, (t >> 3) * 64, (t & 7) * 64, sm);
        SIGNAL(g_x3cnt);
    }

    // ---- P6: final gather-mean (blocks 0-499), gated on all P5 tiles
    if (b < 500) {
        if (tid == 0) {
            while (*(volatile unsigned*)&g_x3cnt < 192u) {}
            __threadfence();
        }
        __syncthreads();
        if (tid < 160) {
            int n = b;
            float s = 0.0f;
#pragma unroll
            for (int kk = 0; kk < KPP; kk++) {
                int i = g_inds_pp[n * KPP + kk];
                s += tgt_feat[tid * N_PTS + i] * g_X3[tid * NSTR + i];
            }
            out[tid * N_PTS + n] = cur_feat[tid * N_PTS + n] + 0.25f * s;
        }
    }
}

// --------------------------------------------------------------------------
extern "C" void kernel_launch(void* const* d_in, const int* in_sizes, int n_in,
                              void* d_out, int out_size) {
    mega_kernel<<<NBLK, NTHR>>>(
        (const float*)d_in[0],  (const float*)d_in[1],
        (const float*)d_in[2],  (const float*)d_in[3],
        (const float*)d_in[4],  (const float*)d_in[5],
        (const float*)d_in[6],  (const float*)d_in[7],
        (const float*)d_in[8],  (const float*)d_in[9],
        (const float*)d_in[10], (const float*)d_in[11],
        (const float*)d_in[12], (const float*)d_in[13],
        (const float*)d_in[14], (const float*)d_in[15],
        (const float*)d_in[16], (const float*)d_in[17],
        (const float*)d_in[18], (const float*)d_in[19],
        (const float*)d_in[20], (const float*)d_in[21],
        (const float*)d_in[22], (const float*)d_in[23],
        (const float*)d_in[24], (const float*)d_in[25],
        (float*)d_out);
}